// round 9
// baseline (speedup 1.0000x reference)
#include <cuda_runtime.h>
#include <cuda_bf16.h>
#include <math.h>
#include <stdint.h>

#define NN 100000
#define EE 1600000
#define HH 128
#define LL 5

// ---------------- device scratch (static; no allocations allowed) ----------
__device__ float g_zcur[NN * HH];
__device__ float g_x0[NN * HH];
__device__ float g_zs[4 * NN * HH];
__device__ __align__(16) uint8_t g_Bh[10 * 32768];
__device__ __align__(16) uint8_t g_Bl[10 * 32768];
__device__ int   g_deg[NN];
__device__ int   g_rowptr[NN + 1];
__device__ int   g_cursor[NN];
__device__ int   g_col[EE];
__device__ int   g_is64;
__device__ int   g_part[128];
__device__ int   g_partoff[128];
__device__ float g_bnsum[HH];
__device__ float g_bnsq[HH];
__device__ float g_bns[HH];
__device__ float g_bnt[HH];

// ---------------- helpers ---------------------------------------------------
__device__ __forceinline__ uint32_t smem_u32(const void* p) {
    uint32_t a;
    asm("{ .reg .u64 t; cvta.to.shared.u64 t, %1; cvt.u32.u64 %0, t; }"
        : "=r"(a) : "l"(p));
    return a;
}

static __device__ __forceinline__ uint32_t pack_bf2(float a, float b) {
    __nv_bfloat162 t = __floats2bfloat162_rn(a, b);
    return *(uint32_t*)&t;
}

__device__ __forceinline__ int swz(int row, int col) {
    return row * 256 + ((((col >> 3) ^ (row & 7)) & 15) << 4) + ((col & 7) << 1);
}

#define LDMX4(r0, r1, r2, r3, addr) \
    asm volatile("ldmatrix.sync.aligned.m8n8.x4.shared.b16 {%0,%1,%2,%3}, [%4];" \
                 : "=r"(r0), "=r"(r1), "=r"(r2), "=r"(r3) : "r"(addr))

#define MMA16816(c, a, b0, b1) \
    asm volatile( \
        "mma.sync.aligned.m16n8k16.row.col.f32.bf16.bf16.f32 " \
        "{%0,%1,%2,%3}, {%4,%5,%6,%7}, {%8,%9}, {%0,%1,%2,%3};" \
        : "+f"((c)[0]), "+f"((c)[1]), "+f"((c)[2]), "+f"((c)[3]) \
        : "r"((a)[0]), "r"((a)[1]), "r"((a)[2]), "r"((a)[3]), "r"(b0), "r"(b1))

// SMEM: A hi/lo 128x128 bf16 (32KB each) + B hi/lo (32KB each) = 128KB
#define SM_AH 0
#define SM_AL 32768
#define SM_BH 65536
#define SM_BL 98304
#define SM_TOTAL 131072

// ---------------- B-tile preparation (once per launch) ----------------------
__global__ __launch_bounds__(256) void prep_b_k(
    const float* __restrict__ W_in, const float* __restrict__ convW,
    const float* __restrict__ W_jk,
    float b0, float b1, float b2, float b3, float b4) {
    int t = blockIdx.x;
    const float* W;
    float wscale, ident;
    if (t == 0) { W = W_in; wscale = 1.f; ident = 0.f; }
    else if (t <= 5) {
        float blv = (t == 1) ? b0 : (t == 2) ? b1 : (t == 3) ? b2 : (t == 4) ? b3 : b4;
        W = convW + (long)(t - 1) * HH * HH;
        wscale = blv; ident = 1.f - blv;
    } else { W = W_jk + (long)(t - 6) * HH * HH; wscale = 1.f; ident = 0.f; }

    int tid = threadIdx.x;
    int n = tid >> 1;
    int kb = (tid & 1) << 6;
    const float* Wb = W + (long)kb * HH + n;
    uint8_t* bh = g_Bh + (long)t * 32768;
    uint8_t* blo = g_Bl + (long)t * 32768;
    #pragma unroll
    for (int jj = 0; jj < 8; jj++) {
        int k0 = kb + jj * 8;
        float vv[8];
        #pragma unroll
        for (int q = 0; q < 8; q++) {
            float w = Wb[(long)(jj * 8 + q) * HH];
            vv[q] = wscale * w + ((k0 + q) == n ? ident : 0.f);
        }
        uint4 hv, lv;
        uint32_t* hp = &hv.x;
        uint32_t* lp = &lv.x;
        #pragma unroll
        for (int q = 0; q < 4; q++) {
            __nv_bfloat16 ha = __float2bfloat16_rn(vv[q * 2]);
            __nv_bfloat16 hb = __float2bfloat16_rn(vv[q * 2 + 1]);
            hp[q] = pack_bf2(__bfloat162float(ha), __bfloat162float(hb));
            lp[q] = pack_bf2(vv[q * 2] - __bfloat162float(ha),
                             vv[q * 2 + 1] - __bfloat162float(hb));
        }
        int so = swz(n, k0);
        *(uint4*)(bh + so) = hv;
        *(uint4*)(blo + so) = lv;
    }
}

// ---------------- standalone GEMM (input layer + JK), 256 thr ---------------
// MODE 0: +bias, copy to C2.  MODE 2: 4 chunks (K=512), +bias.
template <int MODE>
__global__ __launch_bounds__(256, 1) void gemm_tc_k(
    const float* __restrict__ A0, const float* __restrict__ A1,
    const float* __restrict__ A2, const float* __restrict__ A3,
    const float* __restrict__ bias, int tbase,
    float* __restrict__ C, float* __restrict__ C2) {
    extern __shared__ char smem[];
    uint32_t sb = smem_u32(smem);
    const int tid = threadIdx.x;
    const int wid = tid >> 5, lane = tid & 31;
    const int block_row = blockIdx.x * 128;

    const int wm = (wid & 3) * 32;
    const int wn = (wid >> 2) * 64;
    const int lrow = lane & 7, quad = lane >> 3;

    float acc[2][8][4];
    #pragma unroll
    for (int i = 0; i < 2; i++)
        #pragma unroll
        for (int j = 0; j < 8; j++)
            #pragma unroll
            for (int q = 0; q < 4; q++) acc[i][j][q] = 0.f;

    const int NCH = (MODE == 2) ? 4 : 1;
    for (int c = 0; c < NCH; c++) {
        const float* Ab = (c == 0) ? A0 : (c == 1) ? A1 : (c == 2) ? A2 : A3;
        {
            int row = tid >> 1;
            int cb = (tid & 1) << 6;
            int grow = block_row + row;
            const float4* srcp = (const float4*)(Ab + (long)grow * HH + cb);
            #pragma unroll
            for (int jj = 0; jj < 8; jj++) {
                float4 v0 = make_float4(0.f, 0.f, 0.f, 0.f), v1 = v0;
                if (grow < NN) { v0 = srcp[jj * 2]; v1 = srcp[jj * 2 + 1]; }
                __nv_bfloat16 h0 = __float2bfloat16_rn(v0.x);
                __nv_bfloat16 h1 = __float2bfloat16_rn(v0.y);
                __nv_bfloat16 h2 = __float2bfloat16_rn(v0.z);
                __nv_bfloat16 h3 = __float2bfloat16_rn(v0.w);
                __nv_bfloat16 h4 = __float2bfloat16_rn(v1.x);
                __nv_bfloat16 h5 = __float2bfloat16_rn(v1.y);
                __nv_bfloat16 h6 = __float2bfloat16_rn(v1.z);
                __nv_bfloat16 h7 = __float2bfloat16_rn(v1.w);
                uint4 hv, lv;
                hv.x = pack_bf2(__bfloat162float(h0), __bfloat162float(h1));
                hv.y = pack_bf2(__bfloat162float(h2), __bfloat162float(h3));
                hv.z = pack_bf2(__bfloat162float(h4), __bfloat162float(h5));
                hv.w = pack_bf2(__bfloat162float(h6), __bfloat162float(h7));
                lv.x = pack_bf2(v0.x - __bfloat162float(h0), v0.y - __bfloat162float(h1));
                lv.y = pack_bf2(v0.z - __bfloat162float(h2), v0.w - __bfloat162float(h3));
                lv.z = pack_bf2(v1.x - __bfloat162float(h4), v1.y - __bfloat162float(h5));
                lv.w = pack_bf2(v1.z - __bfloat162float(h6), v1.w - __bfloat162float(h7));
                int so = swz(row, cb + jj * 8);
                *(uint4*)(smem + SM_AH + so) = hv;
                *(uint4*)(smem + SM_AL + so) = lv;
            }
        }
        {
            const uint4* bhsrc = (const uint4*)(g_Bh + (long)(tbase + c) * 32768);
            const uint4* blsrc = (const uint4*)(g_Bl + (long)(tbase + c) * 32768);
            uint4* bhdst = (uint4*)(smem + SM_BH);
            uint4* bldst = (uint4*)(smem + SM_BL);
            #pragma unroll
            for (int s = tid; s < 2048; s += 256) {
                bhdst[s] = bhsrc[s];
                bldst[s] = blsrc[s];
            }
        }
        __syncthreads();

        #pragma unroll
        for (int t = 0; t < 3; t++) {
            const uint32_t Aoff = (t == 1) ? SM_AL : SM_AH;
            const uint32_t Boff = (t == 2) ? SM_BL : SM_BH;
            #pragma unroll
            for (int k16 = 0; k16 < 128; k16 += 16) {
                uint32_t a[2][4];
                #pragma unroll
                for (int mt = 0; mt < 2; mt++) {
                    int row = wm + mt * 16 + (quad & 1) * 8 + lrow;
                    int col = k16 + (quad >> 1) * 8;
                    uint32_t addr = sb + Aoff + swz(row, col);
                    LDMX4(a[mt][0], a[mt][1], a[mt][2], a[mt][3], addr);
                }
                #pragma unroll
                for (int nb = 0; nb < 4; nb++) {
                    int row = wn + nb * 16 + (quad >> 1) * 8 + lrow;
                    int col = k16 + (quad & 1) * 8;
                    uint32_t addr = sb + Boff + swz(row, col);
                    uint32_t b0, b1, b2, b3;
                    LDMX4(b0, b1, b2, b3, addr);
                    #pragma unroll
                    for (int mt = 0; mt < 2; mt++) {
                        MMA16816(acc[mt][nb * 2], a[mt], b0, b1);
                        MMA16816(acc[mt][nb * 2 + 1], a[mt], b2, b3);
                    }
                }
            }
        }
        __syncthreads();
    }

    #pragma unroll
    for (int mt = 0; mt < 2; mt++) {
        int r0 = block_row + wm + mt * 16 + (lane >> 2);
        int r1 = r0 + 8;
        #pragma unroll
        for (int nt = 0; nt < 8; nt++) {
            int cb = wn + nt * 8 + (lane & 3) * 2;
            float2 p0, p1;
            p0.x = acc[mt][nt][0]; p0.y = acc[mt][nt][1];
            p1.x = acc[mt][nt][2]; p1.y = acc[mt][nt][3];
            float bx = bias[cb], by = bias[cb + 1];
            p0.x += bx; p0.y += by;
            p1.x += bx; p1.y += by;
            if (r0 < NN) {
                *(float2*)(C + (long)r0 * HH + cb) = p0;
                if (MODE == 0) *(float2*)(C2 + (long)r0 * HH + cb) = p0;
            }
            if (r1 < NN) {
                *(float2*)(C + (long)r1 * HH + cb) = p1;
                if (MODE == 0) *(float2*)(C2 + (long)r1 * HH + cb) = p1;
            }
        }
    }
}

// ---------------- fused layer: gather(+BN) -> bf16 split -> GEMM ------------
// 512 threads, 16 warps.  Warp w gathers rows w*8..w*8+7 of this 128-row tile,
// blends with x0, converts to hi/lo bf16 directly into swizzled A tiles, then
// all warps run the 3-term MMA (warp tile 32x32) and write C (+BN stats).
template <int BNMODE, int STATS>
__global__ __launch_bounds__(512, 1) void fused_layer_k(
    const float* __restrict__ z, const float* __restrict__ x0,
    int tbase, float* __restrict__ C) {
    extern __shared__ char smem[];
    uint32_t sb = smem_u32(smem);
    const int tid = threadIdx.x;
    const int wid = tid >> 5, lane = tid & 31;
    const int block_row = blockIdx.x * 128;

    // ---- B tile copy (independent of gather) ----
    {
        const uint4* bhsrc = (const uint4*)(g_Bh + (long)tbase * 32768);
        const uint4* blsrc = (const uint4*)(g_Bl + (long)tbase * 32768);
        uint4* bhdst = (uint4*)(smem + SM_BH);
        uint4* bldst = (uint4*)(smem + SM_BL);
        #pragma unroll
        for (int s = tid; s < 2048; s += 512) {
            bhdst[s] = bhsrc[s];
            bldst[s] = blsrc[s];
        }
    }

    // ---- gather phase: 8 rows per warp ----
    {
        float4 s4, t4;
        if (BNMODE) {
            s4 = *(const float4*)(g_bns + lane * 4);
            t4 = *(const float4*)(g_bnt + lane * 4);
        }
        #define XF(v) do { if (BNMODE) { \
            (v).x = fmaxf(fmaf((v).x, s4.x, t4.x), 0.f); \
            (v).y = fmaxf(fmaf((v).y, s4.y, t4.y), 0.f); \
            (v).z = fmaxf(fmaf((v).z, s4.z, t4.z), 0.f); \
            (v).w = fmaxf(fmaf((v).w, s4.w, t4.w), 0.f); } } while (0)
        #pragma unroll
        for (int r = 0; r < 8; r++) {
            int row = wid * 8 + r;
            int grow = block_row + row;
            float4 hv = make_float4(0.f, 0.f, 0.f, 0.f);
            if (grow < NN) {
                int beg = g_rowptr[grow], end = g_rowptr[grow + 1];
                float4 acc = make_float4(0.f, 0.f, 0.f, 0.f);
                int e = beg;
                for (; e + 3 < end; e += 4) {
                    int s0 = g_col[e], s1 = g_col[e + 1];
                    int s2 = g_col[e + 2], s3 = g_col[e + 3];
                    float4 v0 = ((const float4*)(z + (long)s0 * HH))[lane];
                    float4 v1 = ((const float4*)(z + (long)s1 * HH))[lane];
                    float4 v2 = ((const float4*)(z + (long)s2 * HH))[lane];
                    float4 v3 = ((const float4*)(z + (long)s3 * HH))[lane];
                    XF(v0); XF(v1); XF(v2); XF(v3);
                    acc.x += (v0.x + v1.x) + (v2.x + v3.x);
                    acc.y += (v0.y + v1.y) + (v2.y + v3.y);
                    acc.z += (v0.z + v1.z) + (v2.z + v3.z);
                    acc.w += (v0.w + v1.w) + (v2.w + v3.w);
                }
                for (; e < end; ++e) {
                    int s = g_col[e];
                    float4 v = ((const float4*)(z + (long)s * HH))[lane];
                    XF(v);
                    acc.x += v.x; acc.y += v.y; acc.z += v.z; acc.w += v.w;
                }
                float4 xv = ((const float4*)(x0 + (long)grow * HH))[lane];
                hv.x = 0.9f * acc.x + 0.1f * xv.x;
                hv.y = 0.9f * acc.y + 0.1f * xv.y;
                hv.z = 0.9f * acc.z + 0.1f * xv.z;
                hv.w = 0.9f * acc.w + 0.1f * xv.w;
            }
            // convert to hi/lo bf16 and store swizzled (cols lane*4..lane*4+3)
            __nv_bfloat16 h0 = __float2bfloat16_rn(hv.x);
            __nv_bfloat16 h1 = __float2bfloat16_rn(hv.y);
            __nv_bfloat16 h2 = __float2bfloat16_rn(hv.z);
            __nv_bfloat16 h3 = __float2bfloat16_rn(hv.w);
            uint2 hh, ll;
            hh.x = pack_bf2(__bfloat162float(h0), __bfloat162float(h1));
            hh.y = pack_bf2(__bfloat162float(h2), __bfloat162float(h3));
            ll.x = pack_bf2(hv.x - __bfloat162float(h0), hv.y - __bfloat162float(h1));
            ll.y = pack_bf2(hv.z - __bfloat162float(h2), hv.w - __bfloat162float(h3));
            int so = swz(row, lane * 4);
            *(uint2*)(smem + SM_AH + so) = hh;
            *(uint2*)(smem + SM_AL + so) = ll;
        }
        #undef XF
    }
    __syncthreads();

    // ---- MMA phase: 16 warps, warp tile 32x32 ----
    const int wm = (wid & 3) * 32;
    const int wn = (wid >> 2) * 32;
    const int lrow = lane & 7, quad = lane >> 3;

    float acc[2][4][4];
    #pragma unroll
    for (int i = 0; i < 2; i++)
        #pragma unroll
        for (int j = 0; j < 4; j++)
            #pragma unroll
            for (int q = 0; q < 4; q++) acc[i][j][q] = 0.f;

    #pragma unroll
    for (int t = 0; t < 3; t++) {
        const uint32_t Aoff = (t == 1) ? SM_AL : SM_AH;
        const uint32_t Boff = (t == 2) ? SM_BL : SM_BH;
        #pragma unroll
        for (int k16 = 0; k16 < 128; k16 += 16) {
            uint32_t a[2][4];
            #pragma unroll
            for (int mt = 0; mt < 2; mt++) {
                int row = wm + mt * 16 + (quad & 1) * 8 + lrow;
                int col = k16 + (quad >> 1) * 8;
                uint32_t addr = sb + Aoff + swz(row, col);
                LDMX4(a[mt][0], a[mt][1], a[mt][2], a[mt][3], addr);
            }
            #pragma unroll
            for (int nb = 0; nb < 2; nb++) {
                int row = wn + nb * 16 + (quad >> 1) * 8 + lrow;
                int col = k16 + (quad & 1) * 8;
                uint32_t addr = sb + Boff + swz(row, col);
                uint32_t b0, b1, b2, b3;
                LDMX4(b0, b1, b2, b3, addr);
                #pragma unroll
                for (int mt = 0; mt < 2; mt++) {
                    MMA16816(acc[mt][nb * 2], a[mt], b0, b1);
                    MMA16816(acc[mt][nb * 2 + 1], a[mt], b2, b3);
                }
            }
        }
    }

    // ---- epilogue: store + optional stats ----
    #pragma unroll
    for (int mt = 0; mt < 2; mt++) {
        int r0 = block_row + wm + mt * 16 + (lane >> 2);
        int r1 = r0 + 8;
        #pragma unroll
        for (int nt = 0; nt < 4; nt++) {
            int cb = wn + nt * 8 + (lane & 3) * 2;
            float2 p0, p1;
            p0.x = acc[mt][nt][0]; p0.y = acc[mt][nt][1];
            p1.x = acc[mt][nt][2]; p1.y = acc[mt][nt][3];
            if (r0 < NN) *(float2*)(C + (long)r0 * HH + cb) = p0;
            if (r1 < NN) *(float2*)(C + (long)r1 * HH + cb) = p1;
        }
    }
    if (STATS) {
        #pragma unroll
        for (int nt = 0; nt < 4; nt++) {
            #pragma unroll
            for (int p = 0; p < 2; p++) {
                float a00 = acc[0][nt][p],     a01 = acc[0][nt][2 + p];
                float a10 = acc[1][nt][p],     a11 = acc[1][nt][2 + p];
                float s = (a00 + a01) + (a10 + a11);
                float q = a00 * a00 + a01 * a01 + a10 * a10 + a11 * a11;
                #pragma unroll
                for (int m = 4; m < 32; m <<= 1) {
                    s += __shfl_xor_sync(0xFFFFFFFFu, s, m);
                    q += __shfl_xor_sync(0xFFFFFFFFu, q, m);
                }
                if (lane < 4) {
                    int cb = wn + nt * 8 + lane * 2 + p;
                    atomicAdd(&g_bnsum[cb], s);
                    atomicAdd(&g_bnsq[cb], q);
                }
            }
        }
    }
}

// ---------------- edge-list helpers ----------------------------------------
__device__ __forceinline__ int edge_at(const void* buf, int e) {
    if (g_is64) return (int)((const long long*)buf)[e];
    return ((const int*)buf)[e];
}

__global__ void detect64_k(const void* srcbuf) {
    const unsigned int* p = (const unsigned int*)srcbuf;
    int any = 0;
    for (int i = 1; i < 512; i += 2) any |= (p[i] != 0u);
    g_is64 = any ? 0 : 1;
}

__global__ void zero_csr_k() {
    int i = blockIdx.x * blockDim.x + threadIdx.x;
    if (i < NN) { g_deg[i] = 0; g_cursor[i] = 0; }
}

__global__ void hist_k(const void* dstbuf) {
    for (int e = blockIdx.x * blockDim.x + threadIdx.x; e < EE;
         e += gridDim.x * blockDim.x) {
        atomicAdd(&g_deg[edge_at(dstbuf, e)], 1);
    }
}

__global__ void scanA_k() {
    __shared__ int wt[32];
    int tid = threadIdx.x, lane = tid & 31, wid = tid >> 5;
    int i = blockIdx.x * 1024 + tid;
    int v = (i < NN) ? g_deg[i] : 0;
    int x = v;
    #pragma unroll
    for (int d = 1; d < 32; d <<= 1) {
        int y = __shfl_up_sync(0xFFFFFFFFu, x, d);
        if (lane >= d) x += y;
    }
    if (lane == 31) wt[wid] = x;
    __syncthreads();
    if (wid == 0) {
        int t = wt[lane];
        int tx = t;
        #pragma unroll
        for (int d = 1; d < 32; d <<= 1) {
            int y = __shfl_up_sync(0xFFFFFFFFu, tx, d);
            if (lane >= d) tx += y;
        }
        wt[lane] = tx - t;
    }
    __syncthreads();
    int incl = x + wt[wid];
    if (i < NN) g_rowptr[i] = incl - v;
    if (tid == 1023) g_part[blockIdx.x] = incl;
}

__global__ void scanB_k(int nblk) {
    int s = 0;
    for (int b = 0; b < nblk; b++) { g_partoff[b] = s; s += g_part[b]; }
    g_rowptr[NN] = s;
}

__global__ void scanC_k() {
    int i = blockIdx.x * 1024 + threadIdx.x;
    if (i < NN) g_rowptr[i] += g_partoff[blockIdx.x];
}

__global__ void fill_k(const void* srcbuf, const void* dstbuf) {
    for (int e = blockIdx.x * blockDim.x + threadIdx.x; e < EE;
         e += gridDim.x * blockDim.x) {
        int d = edge_at(dstbuf, e);
        int s = edge_at(srcbuf, e);
        int pos = atomicAdd(&g_cursor[d], 1);
        g_col[g_rowptr[d] + pos] = s;
    }
}

// ---------------- BatchNorm zero + finalize ---------------------------------
__global__ void zero_bn_k() {
    int c = threadIdx.x;
    g_bnsum[c] = 0.f;
    g_bnsq[c] = 0.f;
}

__global__ void finalize_bn_k(const float* __restrict__ gamma,
                              const float* __restrict__ beta) {
    int c = threadIdx.x;
    float invN = 1.0f / (float)NN;
    float m = g_bnsum[c] * invN;
    float var = g_bnsq[c] * invN - m * m;
    float s = rsqrtf(var + 1e-5f) * gamma[c];
    g_bns[c] = s;
    g_bnt[c] = beta[c] - m * s;
}

// ---------------- host orchestration ----------------------------------------
extern "C" void kernel_launch(void* const* d_in, const int* in_sizes, int n_in,
                              void* d_out, int out_size) {
    const float* x     = (const float*)d_in[0];
    const float* W_in  = (const float*)d_in[1];
    const float* b_in  = (const float*)d_in[2];
    const float* convW = (const float*)d_in[3];
    const float* gma   = (const float*)d_in[4];
    const float* bta   = (const float*)d_in[5];
    const float* W_jk  = (const float*)d_in[6];
    const float* b_jk  = (const float*)d_in[7];
    const void*  src   = d_in[8];
    const void*  dst   = d_in[9];
    float* out = (float*)d_out;

    void *pz, *px0, *pzs;
    cudaGetSymbolAddress(&pz, g_zcur);
    cudaGetSymbolAddress(&px0, g_x0);
    cudaGetSymbolAddress(&pzs, g_zs);
    float* zcur = (float*)pz;
    float* x0   = (float*)px0;
    float* zs0  = (float*)pzs;
    float* zs1  = zs0 + (long)NN * HH;
    float* zs2  = zs1 + (long)NN * HH;
    float* zs3  = zs2 + (long)NN * HH;

    float bl[LL];
    for (int i = 0; i < LL; i++) bl[i] = (float)log(0.5 / (double)(i + 1) + 1.0);

    cudaFuncSetAttribute(gemm_tc_k<0>, cudaFuncAttributeMaxDynamicSharedMemorySize, SM_TOTAL);
    cudaFuncSetAttribute(gemm_tc_k<2>, cudaFuncAttributeMaxDynamicSharedMemorySize, SM_TOTAL);
    cudaFuncSetAttribute(fused_layer_k<0, 0>, cudaFuncAttributeMaxDynamicSharedMemorySize, SM_TOTAL);
    cudaFuncSetAttribute(fused_layer_k<0, 1>, cudaFuncAttributeMaxDynamicSharedMemorySize, SM_TOTAL);
    cudaFuncSetAttribute(fused_layer_k<1, 0>, cudaFuncAttributeMaxDynamicSharedMemorySize, SM_TOTAL);
    cudaFuncSetAttribute(fused_layer_k<1, 1>, cudaFuncAttributeMaxDynamicSharedMemorySize, SM_TOTAL);

    const int GEMM_BLOCKS = (NN + 127) / 128;            // 782
    const int SCAN_BLOCKS = (NN + 1023) / 1024;          // 98

    // ---- forked side stream: CSR build concurrent with prep_b + input GEMM --
    cudaStream_t s2;
    cudaStreamCreateWithFlags(&s2, cudaStreamNonBlocking);
    cudaEvent_t evFork, evJoin;
    cudaEventCreateWithFlags(&evFork, cudaEventDisableTiming);
    cudaEventCreateWithFlags(&evJoin, cudaEventDisableTiming);

    cudaEventRecord(evFork, 0);
    cudaStreamWaitEvent(s2, evFork, 0);

    zero_csr_k<<<(NN + 255) / 256, 256, 0, s2>>>();
    detect64_k<<<1, 1, 0, s2>>>(src);
    hist_k<<<1024, 256, 0, s2>>>(dst);
    scanA_k<<<SCAN_BLOCKS, 1024, 0, s2>>>();
    scanB_k<<<1, 1, 0, s2>>>(SCAN_BLOCKS);
    scanC_k<<<SCAN_BLOCKS, 1024, 0, s2>>>();
    fill_k<<<1024, 256, 0, s2>>>(src, dst);
    cudaEventRecord(evJoin, s2);

    prep_b_k<<<10, 256>>>(W_in, convW, W_jk, bl[0], bl[1], bl[2], bl[3], bl[4]);
    gemm_tc_k<0><<<GEMM_BLOCKS, 256, SM_TOTAL>>>(x, 0, 0, 0, b_in, 0, zcur, x0);

    cudaStreamWaitEvent(0, evJoin, 0);

    float* zsbuf[4] = {zs0, zs1, zs2, zs3};
    const float* gin[LL] = {zcur, zs0, zs1, zs2, zcur};
    for (int i = 0; i < LL; i++) {
        float* Cout = (i < 4) ? zsbuf[i] : out;
        if (i == 0) {
            zero_bn_k<<<1, HH>>>();
            fused_layer_k<0, 1><<<GEMM_BLOCKS, 512, SM_TOTAL>>>(gin[i], x0, 1 + i, Cout);
            finalize_bn_k<<<1, HH>>>(gma + i * HH, bta + i * HH);
        } else if (i <= 2) {
            zero_bn_k<<<1, HH>>>();
            fused_layer_k<1, 1><<<GEMM_BLOCKS, 512, SM_TOTAL>>>(gin[i], x0, 1 + i, Cout);
            finalize_bn_k<<<1, HH>>>(gma + i * HH, bta + i * HH);
        } else if (i == 3) {
            fused_layer_k<1, 0><<<GEMM_BLOCKS, 512, SM_TOTAL>>>(gin[i], x0, 1 + i, Cout);
            gemm_tc_k<2><<<GEMM_BLOCKS, 256, SM_TOTAL>>>(zs0, zs1, zs2, zs3,
                                                         b_jk, 6, zcur, 0);
        } else {
            fused_layer_k<0, 0><<<GEMM_BLOCKS, 512, SM_TOTAL>>>(gin[i], x0, 1 + i, Cout);
        }
    }

    cudaEventDestroy(evFork);
    cudaEventDestroy(evJoin);
    cudaStreamDestroy(s2);
    (void)in_sizes; (void)n_in; (void)out_size;
}

// round 10
// speedup vs baseline: 1.2709x; 1.2709x over previous
#include <cuda_runtime.h>
#include <cuda_bf16.h>
#include <math.h>
#include <stdint.h>

#define NN 100000
#define EE 1600000
#define HH 128
#define LL 5

// ---------------- device scratch (static; no allocations allowed) ----------
__device__ float g_zcur[NN * HH];     // JK output
__device__ float g_x0[NN * HH];       // input-layer output / residual
__device__ float g_h[NN * HH];        // gather output
__device__ float g_zs[4 * NN * HH];
__device__ __align__(16) uint8_t g_Bh[10 * 32768];
__device__ __align__(16) uint8_t g_Bl[10 * 32768];
__device__ int   g_deg[NN];
__device__ int   g_rowptr[NN + 1];
__device__ int   g_cursor[NN];
__device__ int   g_col[EE];
__device__ int   g_is64;
__device__ int   g_part[128];
__device__ int   g_partoff[128];
__device__ float g_bnsum[HH];
__device__ float g_bnsq[HH];
__device__ float g_bns[HH];
__device__ float g_bnt[HH];

// ---------------- helpers ---------------------------------------------------
__device__ __forceinline__ uint32_t smem_u32(const void* p) {
    uint32_t a;
    asm("{ .reg .u64 t; cvta.to.shared.u64 t, %1; cvt.u32.u64 %0, t; }"
        : "=r"(a) : "l"(p));
    return a;
}

static __device__ __forceinline__ uint32_t pack_bf2(float a, float b) {
    __nv_bfloat162 t = __floats2bfloat162_rn(a, b);
    return *(uint32_t*)&t;
}

// XOR-swizzled byte offset inside a (rows x 128) bf16 tile (pitch 256B).
__device__ __forceinline__ int swz(int row, int col) {
    return row * 256 + ((((col >> 3) ^ (row & 7)) & 15) << 4) + ((col & 7) << 1);
}

#define LDMX4(r0, r1, r2, r3, addr) \
    asm volatile("ldmatrix.sync.aligned.m8n8.x4.shared.b16 {%0,%1,%2,%3}, [%4];" \
                 : "=r"(r0), "=r"(r1), "=r"(r2), "=r"(r3) : "r"(addr))

#define MMA16816(c, a, b0, b1) \
    asm volatile( \
        "mma.sync.aligned.m16n8k16.row.col.f32.bf16.bf16.f32 " \
        "{%0,%1,%2,%3}, {%4,%5,%6,%7}, {%8,%9}, {%0,%1,%2,%3};" \
        : "+f"((c)[0]), "+f"((c)[1]), "+f"((c)[2]), "+f"((c)[3]) \
        : "r"((a)[0]), "r"((a)[1]), "r"((a)[2]), "r"((a)[3]), "r"(b0), "r"(b1))

// SMEM: one A tile 128x128 bf16 (32KB) + B hi/lo (32KB each) = 96KB -> 2 CTA/SM
#define SM_A  0
#define SM_BH 32768
#define SM_BL 65536
#define SM_TOTAL 98304

// ---------------- B-tile preparation (once per launch) ----------------------
__global__ __launch_bounds__(256) void prep_b_k(
    const float* __restrict__ W_in, const float* __restrict__ convW,
    const float* __restrict__ W_jk,
    float b0, float b1, float b2, float b3, float b4) {
    int t = blockIdx.x;
    const float* W;
    float wscale, ident;
    if (t == 0) { W = W_in; wscale = 1.f; ident = 0.f; }
    else if (t <= 5) {
        float blv = (t == 1) ? b0 : (t == 2) ? b1 : (t == 3) ? b2 : (t == 4) ? b3 : b4;
        W = convW + (long)(t - 1) * HH * HH;
        wscale = blv; ident = 1.f - blv;
    } else { W = W_jk + (long)(t - 6) * HH * HH; wscale = 1.f; ident = 0.f; }

    int tid = threadIdx.x;
    int n = tid >> 1;
    int kb = (tid & 1) << 6;
    const float* Wb = W + (long)kb * HH + n;
    uint8_t* bh = g_Bh + (long)t * 32768;
    uint8_t* blo = g_Bl + (long)t * 32768;
    #pragma unroll
    for (int jj = 0; jj < 8; jj++) {
        int k0 = kb + jj * 8;
        float vv[8];
        #pragma unroll
        for (int q = 0; q < 8; q++) {
            float w = Wb[(long)(jj * 8 + q) * HH];
            vv[q] = wscale * w + ((k0 + q) == n ? ident : 0.f);
        }
        uint4 hv, lv;
        uint32_t* hp = &hv.x;
        uint32_t* lp = &lv.x;
        #pragma unroll
        for (int q = 0; q < 4; q++) {
            __nv_bfloat16 ha = __float2bfloat16_rn(vv[q * 2]);
            __nv_bfloat16 hb = __float2bfloat16_rn(vv[q * 2 + 1]);
            hp[q] = pack_bf2(__bfloat162float(ha), __bfloat162float(hb));
            lp[q] = pack_bf2(vv[q * 2] - __bfloat162float(ha),
                             vv[q * 2 + 1] - __bfloat162float(hb));
        }
        int so = swz(n, k0);
        *(uint4*)(bh + so) = hv;
        *(uint4*)(blo + so) = lv;
    }
}

// ---------------- A-tile fill: PASS 0 = hi bf16, PASS 1 = lo bf16 -----------
template <int PASS>
__device__ __forceinline__ void fill_a(char* smem, const float* __restrict__ Ab,
                                       int block_row, int tid) {
    int row = tid >> 1;
    int cb = (tid & 1) << 6;
    int grow = block_row + row;
    const float4* srcp = (const float4*)(Ab + (long)grow * HH + cb);
    #pragma unroll
    for (int jj = 0; jj < 8; jj++) {
        float4 v0 = make_float4(0.f, 0.f, 0.f, 0.f), v1 = v0;
        if (grow < NN) { v0 = srcp[jj * 2]; v1 = srcp[jj * 2 + 1]; }
        __nv_bfloat16 h0 = __float2bfloat16_rn(v0.x);
        __nv_bfloat16 h1 = __float2bfloat16_rn(v0.y);
        __nv_bfloat16 h2 = __float2bfloat16_rn(v0.z);
        __nv_bfloat16 h3 = __float2bfloat16_rn(v0.w);
        __nv_bfloat16 h4 = __float2bfloat16_rn(v1.x);
        __nv_bfloat16 h5 = __float2bfloat16_rn(v1.y);
        __nv_bfloat16 h6 = __float2bfloat16_rn(v1.z);
        __nv_bfloat16 h7 = __float2bfloat16_rn(v1.w);
        uint4 ov;
        if (PASS == 0) {
            ov.x = pack_bf2(__bfloat162float(h0), __bfloat162float(h1));
            ov.y = pack_bf2(__bfloat162float(h2), __bfloat162float(h3));
            ov.z = pack_bf2(__bfloat162float(h4), __bfloat162float(h5));
            ov.w = pack_bf2(__bfloat162float(h6), __bfloat162float(h7));
        } else {
            ov.x = pack_bf2(v0.x - __bfloat162float(h0), v0.y - __bfloat162float(h1));
            ov.y = pack_bf2(v0.z - __bfloat162float(h2), v0.w - __bfloat162float(h3));
            ov.z = pack_bf2(v1.x - __bfloat162float(h4), v1.y - __bfloat162float(h5));
            ov.w = pack_bf2(v1.z - __bfloat162float(h6), v1.w - __bfloat162float(h7));
        }
        int so = swz(row, cb + jj * 8);
        *(uint4*)(smem + SM_A + so) = ov;
    }
}

// ---------------- tensor-core GEMM (bf16 split, 128x128 tile, 2 CTA/SM) -----
// Two-pass A buffer: pass1 A=hi -> (A.Bh, A.Bl); pass2 A=lo -> (A.Bh).
// MODE 0: single chunk, +bias.  MODE 1: plain.  MODE 2: 4 chunks, +bias.
// STATS 1: atomicAdd per-column sum/sumsq of C into g_bnsum/g_bnsq.
template <int MODE, int STATS>
__global__ __launch_bounds__(256, 2) void gemm_tc_k(
    const float* __restrict__ A0, const float* __restrict__ A1,
    const float* __restrict__ A2, const float* __restrict__ A3,
    const float* __restrict__ bias, int tbase,
    float* __restrict__ C) {
    extern __shared__ char smem[];
    uint32_t sb = smem_u32(smem);
    const int tid = threadIdx.x;
    const int wid = tid >> 5, lane = tid & 31;
    const int block_row = blockIdx.x * 128;

    const int wm = (wid & 3) * 32;
    const int wn = (wid >> 2) * 64;
    const int lrow = lane & 7, quad = lane >> 3;

    float acc[2][8][4];
    #pragma unroll
    for (int i = 0; i < 2; i++)
        #pragma unroll
        for (int j = 0; j < 8; j++)
            #pragma unroll
            for (int q = 0; q < 4; q++) acc[i][j][q] = 0.f;

    const int NCH = (MODE == 2) ? 4 : 1;
    for (int c = 0; c < NCH; c++) {
        const float* Ab = (c == 0) ? A0 : (c == 1) ? A1 : (c == 2) ? A2 : A3;

        // ---- pass 1: A = hi ----
        fill_a<0>(smem, Ab, block_row, tid);
        {
            const uint4* bhsrc = (const uint4*)(g_Bh + (long)(tbase + c) * 32768);
            const uint4* blsrc = (const uint4*)(g_Bl + (long)(tbase + c) * 32768);
            uint4* bhdst = (uint4*)(smem + SM_BH);
            uint4* bldst = (uint4*)(smem + SM_BL);
            #pragma unroll
            for (int s = tid; s < 2048; s += 256) {
                bhdst[s] = bhsrc[s];
                bldst[s] = blsrc[s];
            }
        }
        __syncthreads();
        #pragma unroll
        for (int t = 0; t < 2; t++) {
            const uint32_t Boff = (t == 0) ? SM_BH : SM_BL;
            #pragma unroll
            for (int k16 = 0; k16 < 128; k16 += 16) {
                uint32_t a[2][4];
                #pragma unroll
                for (int mt = 0; mt < 2; mt++) {
                    int row = wm + mt * 16 + (quad & 1) * 8 + lrow;
                    int col = k16 + (quad >> 1) * 8;
                    uint32_t addr = sb + SM_A + swz(row, col);
                    LDMX4(a[mt][0], a[mt][1], a[mt][2], a[mt][3], addr);
                }
                #pragma unroll
                for (int nb = 0; nb < 4; nb++) {
                    int row = wn + nb * 16 + (quad >> 1) * 8 + lrow;
                    int col = k16 + (quad & 1) * 8;
                    uint32_t addr = sb + Boff + swz(row, col);
                    uint32_t b0, b1, b2, b3;
                    LDMX4(b0, b1, b2, b3, addr);
                    #pragma unroll
                    for (int mt = 0; mt < 2; mt++) {
                        MMA16816(acc[mt][nb * 2], a[mt], b0, b1);
                        MMA16816(acc[mt][nb * 2 + 1], a[mt], b2, b3);
                    }
                }
            }
        }
        __syncthreads();

        // ---- pass 2: A = lo, term Al.Bh ----
        fill_a<1>(smem, Ab, block_row, tid);
        __syncthreads();
        #pragma unroll
        for (int k16 = 0; k16 < 128; k16 += 16) {
            uint32_t a[2][4];
            #pragma unroll
            for (int mt = 0; mt < 2; mt++) {
                int row = wm + mt * 16 + (quad & 1) * 8 + lrow;
                int col = k16 + (quad >> 1) * 8;
                uint32_t addr = sb + SM_A + swz(row, col);
                LDMX4(a[mt][0], a[mt][1], a[mt][2], a[mt][3], addr);
            }
            #pragma unroll
            for (int nb = 0; nb < 4; nb++) {
                int row = wn + nb * 16 + (quad >> 1) * 8 + lrow;
                int col = k16 + (quad & 1) * 8;
                uint32_t addr = sb + SM_BH + swz(row, col);
                uint32_t b0, b1, b2, b3;
                LDMX4(b0, b1, b2, b3, addr);
                #pragma unroll
                for (int mt = 0; mt < 2; mt++) {
                    MMA16816(acc[mt][nb * 2], a[mt], b0, b1);
                    MMA16816(acc[mt][nb * 2 + 1], a[mt], b2, b3);
                }
            }
        }
        __syncthreads();
    }

    // ---- epilogue: store ----
    #pragma unroll
    for (int mt = 0; mt < 2; mt++) {
        int r0 = block_row + wm + mt * 16 + (lane >> 2);
        int r1 = r0 + 8;
        #pragma unroll
        for (int nt = 0; nt < 8; nt++) {
            int cb = wn + nt * 8 + (lane & 3) * 2;
            float2 p0, p1;
            p0.x = acc[mt][nt][0]; p0.y = acc[mt][nt][1];
            p1.x = acc[mt][nt][2]; p1.y = acc[mt][nt][3];
            if (MODE != 1) {
                float bx = bias[cb], by = bias[cb + 1];
                p0.x += bx; p0.y += by;
                p1.x += bx; p1.y += by;
            }
            if (r0 < NN) *(float2*)(C + (long)r0 * HH + cb) = p0;
            if (r1 < NN) *(float2*)(C + (long)r1 * HH + cb) = p1;
        }
    }
    // ---- epilogue: fused BN statistics ----
    if (STATS) {
        #pragma unroll
        for (int nt = 0; nt < 8; nt++) {
            #pragma unroll
            for (int p = 0; p < 2; p++) {
                float a00 = acc[0][nt][p],     a01 = acc[0][nt][2 + p];
                float a10 = acc[1][nt][p],     a11 = acc[1][nt][2 + p];
                float s = (a00 + a01) + (a10 + a11);
                float q = a00 * a00 + a01 * a01 + a10 * a10 + a11 * a11;
                #pragma unroll
                for (int m = 4; m < 32; m <<= 1) {
                    s += __shfl_xor_sync(0xFFFFFFFFu, s, m);
                    q += __shfl_xor_sync(0xFFFFFFFFu, q, m);
                }
                if (lane < 4) {
                    int cb = wn + nt * 8 + lane * 2 + p;
                    atomicAdd(&g_bnsum[cb], s);
                    atomicAdd(&g_bnsq[cb], q);
                }
            }
        }
    }
}

// ---------------- edge-list helpers ----------------------------------------
__device__ __forceinline__ int edge_at(const void* buf, int e) {
    if (g_is64) return (int)((const long long*)buf)[e];
    return ((const int*)buf)[e];
}

__global__ void detect64_k(const void* srcbuf) {
    const unsigned int* p = (const unsigned int*)srcbuf;
    int any = 0;
    for (int i = 1; i < 512; i += 2) any |= (p[i] != 0u);
    g_is64 = any ? 0 : 1;
}

__global__ void zero_csr_k() {
    int i = blockIdx.x * blockDim.x + threadIdx.x;
    if (i < NN) { g_deg[i] = 0; g_cursor[i] = 0; }
}

__global__ void hist_k(const void* dstbuf) {
    for (int e = blockIdx.x * blockDim.x + threadIdx.x; e < EE;
         e += gridDim.x * blockDim.x) {
        atomicAdd(&g_deg[edge_at(dstbuf, e)], 1);
    }
}

__global__ void scanA_k() {
    __shared__ int wt[32];
    int tid = threadIdx.x, lane = tid & 31, wid = tid >> 5;
    int i = blockIdx.x * 1024 + tid;
    int v = (i < NN) ? g_deg[i] : 0;
    int x = v;
    #pragma unroll
    for (int d = 1; d < 32; d <<= 1) {
        int y = __shfl_up_sync(0xFFFFFFFFu, x, d);
        if (lane >= d) x += y;
    }
    if (lane == 31) wt[wid] = x;
    __syncthreads();
    if (wid == 0) {
        int t = wt[lane];
        int tx = t;
        #pragma unroll
        for (int d = 1; d < 32; d <<= 1) {
            int y = __shfl_up_sync(0xFFFFFFFFu, tx, d);
            if (lane >= d) tx += y;
        }
        wt[lane] = tx - t;
    }
    __syncthreads();
    int incl = x + wt[wid];
    if (i < NN) g_rowptr[i] = incl - v;
    if (tid == 1023) g_part[blockIdx.x] = incl;
}

__global__ void scanB_k(int nblk) {
    int s = 0;
    for (int b = 0; b < nblk; b++) { g_partoff[b] = s; s += g_part[b]; }
    g_rowptr[NN] = s;
}

__global__ void scanC_k() {
    int i = blockIdx.x * 1024 + threadIdx.x;
    if (i < NN) g_rowptr[i] += g_partoff[blockIdx.x];
}

__global__ void fill_k(const void* srcbuf, const void* dstbuf) {
    for (int e = blockIdx.x * blockDim.x + threadIdx.x; e < EE;
         e += gridDim.x * blockDim.x) {
        int d = edge_at(dstbuf, e);
        int s = edge_at(srcbuf, e);
        int pos = atomicAdd(&g_cursor[d], 1);
        g_col[g_rowptr[d] + pos] = s;
    }
}

// ------ gather: h = 0.9 * sum_src f(z[src]) + 0.1 * x0 ----------------------
template <int BNMODE>
__global__ void gather_k(const float* __restrict__ z,
                         const float* __restrict__ x0,
                         float* __restrict__ h) {
    int gw = (blockIdx.x * blockDim.x + threadIdx.x) >> 5;
    if (gw >= NN) return;
    int lane = threadIdx.x & 31;
    float4 s4, t4;
    if (BNMODE) {
        s4 = *(const float4*)(g_bns + lane * 4);
        t4 = *(const float4*)(g_bnt + lane * 4);
    }
    int beg = g_rowptr[gw], end = g_rowptr[gw + 1];
    float4 acc = make_float4(0.f, 0.f, 0.f, 0.f);
    int e = beg;
    #define XF(v) do { if (BNMODE) { \
        (v).x = fmaxf(fmaf((v).x, s4.x, t4.x), 0.f); \
        (v).y = fmaxf(fmaf((v).y, s4.y, t4.y), 0.f); \
        (v).z = fmaxf(fmaf((v).z, s4.z, t4.z), 0.f); \
        (v).w = fmaxf(fmaf((v).w, s4.w, t4.w), 0.f); } } while (0)
    for (; e + 3 < end; e += 4) {
        int s0 = g_col[e], s1 = g_col[e + 1], s2 = g_col[e + 2], s3 = g_col[e + 3];
        float4 v0 = ((const float4*)(z + (long)s0 * HH))[lane];
        float4 v1 = ((const float4*)(z + (long)s1 * HH))[lane];
        float4 v2 = ((const float4*)(z + (long)s2 * HH))[lane];
        float4 v3 = ((const float4*)(z + (long)s3 * HH))[lane];
        XF(v0); XF(v1); XF(v2); XF(v3);
        acc.x += (v0.x + v1.x) + (v2.x + v3.x);
        acc.y += (v0.y + v1.y) + (v2.y + v3.y);
        acc.z += (v0.z + v1.z) + (v2.z + v3.z);
        acc.w += (v0.w + v1.w) + (v2.w + v3.w);
    }
    for (; e < end; ++e) {
        int s = g_col[e];
        float4 v = ((const float4*)(z + (long)s * HH))[lane];
        XF(v);
        acc.x += v.x; acc.y += v.y; acc.z += v.z; acc.w += v.w;
    }
    #undef XF
    float4 xv = ((const float4*)(x0 + (long)gw * HH))[lane];
    float4 o;
    const float A1 = 0.9f, A0 = 0.1f;
    o.x = A1 * acc.x + A0 * xv.x;
    o.y = A1 * acc.y + A0 * xv.y;
    o.z = A1 * acc.z + A0 * xv.z;
    o.w = A1 * acc.w + A0 * xv.w;
    ((float4*)(h + (long)gw * HH))[lane] = o;
}

// ---------------- BatchNorm zero + finalize ---------------------------------
__global__ void zero_bn_k() {
    int c = threadIdx.x;
    g_bnsum[c] = 0.f;
    g_bnsq[c] = 0.f;
}

__global__ void finalize_bn_k(const float* __restrict__ gamma,
                              const float* __restrict__ beta) {
    int c = threadIdx.x;
    float invN = 1.0f / (float)NN;
    float m = g_bnsum[c] * invN;
    float var = g_bnsq[c] * invN - m * m;
    float s = rsqrtf(var + 1e-5f) * gamma[c];
    g_bns[c] = s;
    g_bnt[c] = beta[c] - m * s;
}

// ---------------- host orchestration ----------------------------------------
extern "C" void kernel_launch(void* const* d_in, const int* in_sizes, int n_in,
                              void* d_out, int out_size) {
    const float* x     = (const float*)d_in[0];
    const float* W_in  = (const float*)d_in[1];
    const float* b_in  = (const float*)d_in[2];
    const float* convW = (const float*)d_in[3];
    const float* gma   = (const float*)d_in[4];
    const float* bta   = (const float*)d_in[5];
    const float* W_jk  = (const float*)d_in[6];
    const float* b_jk  = (const float*)d_in[7];
    const void*  src   = d_in[8];
    const void*  dst   = d_in[9];
    float* out = (float*)d_out;

    void *pz, *px0, *ph, *pzs;
    cudaGetSymbolAddress(&pz, g_zcur);
    cudaGetSymbolAddress(&px0, g_x0);
    cudaGetSymbolAddress(&ph, g_h);
    cudaGetSymbolAddress(&pzs, g_zs);
    float* zcur = (float*)pz;
    float* x0   = (float*)px0;
    float* h    = (float*)ph;
    float* zs0  = (float*)pzs;
    float* zs1  = zs0 + (long)NN * HH;
    float* zs2  = zs1 + (long)NN * HH;
    float* zs3  = zs2 + (long)NN * HH;

    float bl[LL];
    for (int i = 0; i < LL; i++) bl[i] = (float)log(0.5 / (double)(i + 1) + 1.0);

    cudaFuncSetAttribute(gemm_tc_k<0, 0>, cudaFuncAttributeMaxDynamicSharedMemorySize, SM_TOTAL);
    cudaFuncSetAttribute(gemm_tc_k<1, 0>, cudaFuncAttributeMaxDynamicSharedMemorySize, SM_TOTAL);
    cudaFuncSetAttribute(gemm_tc_k<1, 1>, cudaFuncAttributeMaxDynamicSharedMemorySize, SM_TOTAL);
    cudaFuncSetAttribute(gemm_tc_k<2, 0>, cudaFuncAttributeMaxDynamicSharedMemorySize, SM_TOTAL);

    const int GEMM_BLOCKS = (NN + 127) / 128;            // 782
    const int GATHER_BLOCKS = (NN * 32 + 255) / 256;
    const int SCAN_BLOCKS = (NN + 1023) / 1024;          // 98

    // ---- forked side stream: CSR build concurrent with prep_b + input GEMM --
    cudaStream_t s2;
    cudaStreamCreateWithFlags(&s2, cudaStreamNonBlocking);
    cudaEvent_t evFork, evJoin;
    cudaEventCreateWithFlags(&evFork, cudaEventDisableTiming);
    cudaEventCreateWithFlags(&evJoin, cudaEventDisableTiming);

    cudaEventRecord(evFork, 0);
    cudaStreamWaitEvent(s2, evFork, 0);

    zero_csr_k<<<(NN + 255) / 256, 256, 0, s2>>>();
    detect64_k<<<1, 1, 0, s2>>>(src);
    hist_k<<<1024, 256, 0, s2>>>(dst);
    scanA_k<<<SCAN_BLOCKS, 1024, 0, s2>>>();
    scanB_k<<<1, 1, 0, s2>>>(SCAN_BLOCKS);
    scanC_k<<<SCAN_BLOCKS, 1024, 0, s2>>>();
    fill_k<<<1024, 256, 0, s2>>>(src, dst);
    cudaEventRecord(evJoin, s2);

    // main stream: B-tile prep + input GEMM (z0 == x0, single buffer)
    prep_b_k<<<10, 256>>>(W_in, convW, W_jk, bl[0], bl[1], bl[2], bl[3], bl[4]);
    gemm_tc_k<0, 0><<<GEMM_BLOCKS, 256, SM_TOTAL>>>(x, 0, 0, 0, b_in, 0, x0);

    cudaStreamWaitEvent(0, evJoin, 0);

    float* zsbuf[4] = {zs0, zs1, zs2, zs3};
    const float* gin[LL] = {x0, zs0, zs1, zs2, zcur};
    for (int i = 0; i < LL; i++) {
        if (i >= 1 && i <= 3)
            gather_k<1><<<GATHER_BLOCKS, 256>>>(gin[i], x0, h);
        else
            gather_k<0><<<GATHER_BLOCKS, 256>>>(gin[i], x0, h);
        float* Cout = (i < 4) ? zsbuf[i] : out;
        if (i < 3) {
            zero_bn_k<<<1, HH>>>();
            gemm_tc_k<1, 1><<<GEMM_BLOCKS, 256, SM_TOTAL>>>(h, 0, 0, 0, 0, 1 + i, Cout);
            finalize_bn_k<<<1, HH>>>(gma + i * HH, bta + i * HH);
        } else {
            gemm_tc_k<1, 0><<<GEMM_BLOCKS, 256, SM_TOTAL>>>(h, 0, 0, 0, 0, 1 + i, Cout);
        }
        if (i == 3) {
            gemm_tc_k<2, 0><<<GEMM_BLOCKS, 256, SM_TOTAL>>>(zs0, zs1, zs2, zs3,
                                                            b_jk, 6, zcur);
        }
    }

    cudaEventDestroy(evFork);
    cudaEventDestroy(evJoin);
    cudaStreamDestroy(s2);
    (void)in_sizes; (void)n_in; (void)out_size;
}

// round 11
// speedup vs baseline: 1.4806x; 1.1650x over previous
#include <cuda_runtime.h>
#include <cuda_bf16.h>
#include <cuda_fp16.h>
#include <math.h>
#include <stdint.h>

#define NN 100000
#define EE 1600000
#define HH 128
#define LL 5

// ---------------- device scratch (static; no allocations allowed) ----------
__device__ float g_x0[NN * HH];       // input-layer output / residual
__device__ float g_h[NN * HH];        // gather output
__device__ float g_zs[4 * NN * HH];   // conv outputs (fp32, feed JK)
__device__ __align__(16) __half g_zh[5 * NN * HH];  // fp16 copies for gathers
__device__ __align__(16) uint8_t g_Bh[10 * 32768];
__device__ __align__(16) uint8_t g_Bl[10 * 32768];
__device__ int   g_deg[NN];
__device__ int   g_rowptr[NN + 1];
__device__ int   g_cursor[NN];
__device__ int   g_col[EE];
__device__ int   g_is64;
__device__ int   g_part[128];
__device__ int   g_partoff[128];
__device__ float g_bnsum[HH];
__device__ float g_bnsq[HH];
__device__ float g_bns[HH];
__device__ float g_bnt[HH];

// ---------------- helpers ---------------------------------------------------
__device__ __forceinline__ uint32_t smem_u32(const void* p) {
    uint32_t a;
    asm("{ .reg .u64 t; cvta.to.shared.u64 t, %1; cvt.u32.u64 %0, t; }"
        : "=r"(a) : "l"(p));
    return a;
}

static __device__ __forceinline__ uint32_t pack_bf2(float a, float b) {
    __nv_bfloat162 t = __floats2bfloat162_rn(a, b);
    return *(uint32_t*)&t;
}

// XOR-swizzled byte offset inside a (rows x 128) bf16 tile (pitch 256B).
__device__ __forceinline__ int swz(int row, int col) {
    return row * 256 + ((((col >> 3) ^ (row & 7)) & 15) << 4) + ((col & 7) << 1);
}

#define LDMX4(r0, r1, r2, r3, addr) \
    asm volatile("ldmatrix.sync.aligned.m8n8.x4.shared.b16 {%0,%1,%2,%3}, [%4];" \
                 : "=r"(r0), "=r"(r1), "=r"(r2), "=r"(r3) : "r"(addr))

#define MMA16816(c, a, b0, b1) \
    asm volatile( \
        "mma.sync.aligned.m16n8k16.row.col.f32.bf16.bf16.f32 " \
        "{%0,%1,%2,%3}, {%4,%5,%6,%7}, {%8,%9}, {%0,%1,%2,%3};" \
        : "+f"((c)[0]), "+f"((c)[1]), "+f"((c)[2]), "+f"((c)[3]) \
        : "r"((a)[0]), "r"((a)[1]), "r"((a)[2]), "r"((a)[3]), "r"(b0), "r"(b1))

// SMEM: A hi/lo 128x128 bf16 (32KB each) + B hi/lo (32KB each) = 128KB
#define SM_AH 0
#define SM_AL 32768
#define SM_BH 65536
#define SM_BL 98304
#define SM_TOTAL 131072

// ---------------- B-tile preparation (once per launch) ----------------------
__global__ __launch_bounds__(256) void prep_b_k(
    const float* __restrict__ W_in, const float* __restrict__ convW,
    const float* __restrict__ W_jk,
    float b0, float b1, float b2, float b3, float b4) {
    int t = blockIdx.x;
    const float* W;
    float wscale, ident;
    if (t == 0) { W = W_in; wscale = 1.f; ident = 0.f; }
    else if (t <= 5) {
        float blv = (t == 1) ? b0 : (t == 2) ? b1 : (t == 3) ? b2 : (t == 4) ? b3 : b4;
        W = convW + (long)(t - 1) * HH * HH;
        wscale = blv; ident = 1.f - blv;
    } else { W = W_jk + (long)(t - 6) * HH * HH; wscale = 1.f; ident = 0.f; }

    int tid = threadIdx.x;
    int n = tid >> 1;
    int kb = (tid & 1) << 6;
    const float* Wb = W + (long)kb * HH + n;
    uint8_t* bh = g_Bh + (long)t * 32768;
    uint8_t* blo = g_Bl + (long)t * 32768;
    #pragma unroll
    for (int jj = 0; jj < 8; jj++) {
        int k0 = kb + jj * 8;
        float vv[8];
        #pragma unroll
        for (int q = 0; q < 8; q++) {
            float w = Wb[(long)(jj * 8 + q) * HH];
            vv[q] = wscale * w + ((k0 + q) == n ? ident : 0.f);
        }
        uint4 hv, lv;
        uint32_t* hp = &hv.x;
        uint32_t* lp = &lv.x;
        #pragma unroll
        for (int q = 0; q < 4; q++) {
            __nv_bfloat16 ha = __float2bfloat16_rn(vv[q * 2]);
            __nv_bfloat16 hb = __float2bfloat16_rn(vv[q * 2 + 1]);
            hp[q] = pack_bf2(__bfloat162float(ha), __bfloat162float(hb));
            lp[q] = pack_bf2(vv[q * 2] - __bfloat162float(ha),
                             vv[q * 2 + 1] - __bfloat162float(hb));
        }
        int so = swz(n, k0);
        *(uint4*)(bh + so) = hv;
        *(uint4*)(blo + so) = lv;
    }
}

// ---------------- tensor-core GEMM (mma.sync bf16 split, 128x128 tile) ------
// MODE 0/1: single chunk (0 adds bias).  MODE 2: 4 chunks (K=512), +bias.
// STATS 1: atomicAdd per-column sum/sumsq of C into g_bnsum/g_bnsq.
// C (fp32) and Ch (fp16 copy) are independently nullable.
template <int MODE, int STATS>
__global__ __launch_bounds__(256, 1) void gemm_tc_k(
    const float* __restrict__ A0, const float* __restrict__ A1,
    const float* __restrict__ A2, const float* __restrict__ A3,
    const float* __restrict__ bias, int tbase,
    float* __restrict__ C, __half* __restrict__ Ch) {
    extern __shared__ char smem[];
    uint32_t sb = smem_u32(smem);
    const int tid = threadIdx.x;
    const int wid = tid >> 5, lane = tid & 31;
    const int block_row = blockIdx.x * 128;

    const int wm = (wid & 3) * 32;
    const int wn = (wid >> 2) * 64;
    const int lrow = lane & 7, quad = lane >> 3;

    float acc[2][8][4];
    #pragma unroll
    for (int i = 0; i < 2; i++)
        #pragma unroll
        for (int j = 0; j < 8; j++)
            #pragma unroll
            for (int q = 0; q < 4; q++) acc[i][j][q] = 0.f;

    const int NCH = (MODE == 2) ? 4 : 1;
    for (int c = 0; c < NCH; c++) {
        const float* Ab = (c == 0) ? A0 : (c == 1) ? A1 : (c == 2) ? A2 : A3;
        // ---- A tile fill: fp32 -> (hi, lo) bf16, swizzled ----
        {
            int row = tid >> 1;
            int cb = (tid & 1) << 6;
            int grow = block_row + row;
            const float4* srcp = (const float4*)(Ab + (long)grow * HH + cb);
            #pragma unroll
            for (int jj = 0; jj < 8; jj++) {
                float4 v0 = make_float4(0.f, 0.f, 0.f, 0.f), v1 = v0;
                if (grow < NN) { v0 = srcp[jj * 2]; v1 = srcp[jj * 2 + 1]; }
                __nv_bfloat16 h0 = __float2bfloat16_rn(v0.x);
                __nv_bfloat16 h1 = __float2bfloat16_rn(v0.y);
                __nv_bfloat16 h2 = __float2bfloat16_rn(v0.z);
                __nv_bfloat16 h3 = __float2bfloat16_rn(v0.w);
                __nv_bfloat16 h4 = __float2bfloat16_rn(v1.x);
                __nv_bfloat16 h5 = __float2bfloat16_rn(v1.y);
                __nv_bfloat16 h6 = __float2bfloat16_rn(v1.z);
                __nv_bfloat16 h7 = __float2bfloat16_rn(v1.w);
                uint4 hv, lv;
                hv.x = pack_bf2(__bfloat162float(h0), __bfloat162float(h1));
                hv.y = pack_bf2(__bfloat162float(h2), __bfloat162float(h3));
                hv.z = pack_bf2(__bfloat162float(h4), __bfloat162float(h5));
                hv.w = pack_bf2(__bfloat162float(h6), __bfloat162float(h7));
                lv.x = pack_bf2(v0.x - __bfloat162float(h0), v0.y - __bfloat162float(h1));
                lv.y = pack_bf2(v0.z - __bfloat162float(h2), v0.w - __bfloat162float(h3));
                lv.z = pack_bf2(v1.x - __bfloat162float(h4), v1.y - __bfloat162float(h5));
                lv.w = pack_bf2(v1.z - __bfloat162float(h6), v1.w - __bfloat162float(h7));
                int so = swz(row, cb + jj * 8);
                *(uint4*)(smem + SM_AH + so) = hv;
                *(uint4*)(smem + SM_AL + so) = lv;
            }
        }
        // ---- B tile fill: straight copy of preconverted swizzled images ----
        {
            const uint4* bhsrc = (const uint4*)(g_Bh + (long)(tbase + c) * 32768);
            const uint4* blsrc = (const uint4*)(g_Bl + (long)(tbase + c) * 32768);
            uint4* bhdst = (uint4*)(smem + SM_BH);
            uint4* bldst = (uint4*)(smem + SM_BL);
            #pragma unroll
            for (int s = tid; s < 2048; s += 256) {
                bhdst[s] = bhsrc[s];
                bldst[s] = blsrc[s];
            }
        }
        __syncthreads();

        // ---- compute: 3 split terms (AhBh, AlBh, AhBl) ----
        #pragma unroll
        for (int t = 0; t < 3; t++) {
            const uint32_t Aoff = (t == 1) ? SM_AL : SM_AH;
            const uint32_t Boff = (t == 2) ? SM_BL : SM_BH;
            #pragma unroll
            for (int k16 = 0; k16 < 128; k16 += 16) {
                uint32_t a[2][4];
                #pragma unroll
                for (int mt = 0; mt < 2; mt++) {
                    int row = wm + mt * 16 + (quad & 1) * 8 + lrow;
                    int col = k16 + (quad >> 1) * 8;
                    uint32_t addr = sb + Aoff + swz(row, col);
                    LDMX4(a[mt][0], a[mt][1], a[mt][2], a[mt][3], addr);
                }
                #pragma unroll
                for (int nb = 0; nb < 4; nb++) {
                    int row = wn + nb * 16 + (quad >> 1) * 8 + lrow;
                    int col = k16 + (quad & 1) * 8;
                    uint32_t addr = sb + Boff + swz(row, col);
                    uint32_t b0, b1, b2, b3;
                    LDMX4(b0, b1, b2, b3, addr);
                    #pragma unroll
                    for (int mt = 0; mt < 2; mt++) {
                        MMA16816(acc[mt][nb * 2], a[mt], b0, b1);
                        MMA16816(acc[mt][nb * 2 + 1], a[mt], b2, b3);
                    }
                }
            }
        }
        __syncthreads();
    }

    // ---- epilogue: store fp32 (+ fp16 copy) ----
    #pragma unroll
    for (int mt = 0; mt < 2; mt++) {
        int r0 = block_row + wm + mt * 16 + (lane >> 2);
        int r1 = r0 + 8;
        #pragma unroll
        for (int nt = 0; nt < 8; nt++) {
            int cb = wn + nt * 8 + (lane & 3) * 2;
            float2 p0, p1;
            p0.x = acc[mt][nt][0]; p0.y = acc[mt][nt][1];
            p1.x = acc[mt][nt][2]; p1.y = acc[mt][nt][3];
            if (MODE != 1) {
                float bx = bias[cb], by = bias[cb + 1];
                p0.x += bx; p0.y += by;
                p1.x += bx; p1.y += by;
            }
            if (r0 < NN) {
                if (C)  *(float2*)(C + (long)r0 * HH + cb) = p0;
                if (Ch) *(__half2*)(Ch + (long)r0 * HH + cb) = __floats2half2_rn(p0.x, p0.y);
            }
            if (r1 < NN) {
                if (C)  *(float2*)(C + (long)r1 * HH + cb) = p1;
                if (Ch) *(__half2*)(Ch + (long)r1 * HH + cb) = __floats2half2_rn(p1.x, p1.y);
            }
        }
    }
    // ---- epilogue: fused BN statistics (padded rows contribute exact 0) ----
    if (STATS) {
        #pragma unroll
        for (int nt = 0; nt < 8; nt++) {
            #pragma unroll
            for (int p = 0; p < 2; p++) {
                float a00 = acc[0][nt][p],     a01 = acc[0][nt][2 + p];
                float a10 = acc[1][nt][p],     a11 = acc[1][nt][2 + p];
                float s = (a00 + a01) + (a10 + a11);
                float q = a00 * a00 + a01 * a01 + a10 * a10 + a11 * a11;
                #pragma unroll
                for (int m = 4; m < 32; m <<= 1) {
                    s += __shfl_xor_sync(0xFFFFFFFFu, s, m);
                    q += __shfl_xor_sync(0xFFFFFFFFu, q, m);
                }
                if (lane < 4) {
                    int cb = wn + nt * 8 + lane * 2 + p;
                    atomicAdd(&g_bnsum[cb], s);
                    atomicAdd(&g_bnsq[cb], q);
                }
            }
        }
    }
}

// ---------------- edge-list helpers ----------------------------------------
__device__ __forceinline__ int edge_at(const void* buf, int e) {
    if (g_is64) return (int)((const long long*)buf)[e];
    return ((const int*)buf)[e];
}

__global__ void detect64_k(const void* srcbuf) {
    const unsigned int* p = (const unsigned int*)srcbuf;
    int any = 0;
    for (int i = 1; i < 512; i += 2) any |= (p[i] != 0u);
    g_is64 = any ? 0 : 1;
}

__global__ void zero_csr_k() {
    int i = blockIdx.x * blockDim.x + threadIdx.x;
    if (i < NN) { g_deg[i] = 0; g_cursor[i] = 0; }
}

__global__ void hist_k(const void* dstbuf) {
    for (int e = blockIdx.x * blockDim.x + threadIdx.x; e < EE;
         e += gridDim.x * blockDim.x) {
        atomicAdd(&g_deg[edge_at(dstbuf, e)], 1);
    }
}

__global__ void scanA_k() {
    __shared__ int wt[32];
    int tid = threadIdx.x, lane = tid & 31, wid = tid >> 5;
    int i = blockIdx.x * 1024 + tid;
    int v = (i < NN) ? g_deg[i] : 0;
    int x = v;
    #pragma unroll
    for (int d = 1; d < 32; d <<= 1) {
        int y = __shfl_up_sync(0xFFFFFFFFu, x, d);
        if (lane >= d) x += y;
    }
    if (lane == 31) wt[wid] = x;
    __syncthreads();
    if (wid == 0) {
        int t = wt[lane];
        int tx = t;
        #pragma unroll
        for (int d = 1; d < 32; d <<= 1) {
            int y = __shfl_up_sync(0xFFFFFFFFu, tx, d);
            if (lane >= d) tx += y;
        }
        wt[lane] = tx - t;
    }
    __syncthreads();
    int incl = x + wt[wid];
    if (i < NN) g_rowptr[i] = incl - v;
    if (tid == 1023) g_part[blockIdx.x] = incl;
}

__global__ void scanB_k(int nblk) {
    int s = 0;
    for (int b = 0; b < nblk; b++) { g_partoff[b] = s; s += g_part[b]; }
    g_rowptr[NN] = s;
}

__global__ void scanC_k() {
    int i = blockIdx.x * 1024 + threadIdx.x;
    if (i < NN) g_rowptr[i] += g_partoff[blockIdx.x];
}

__global__ void fill_k(const void* srcbuf, const void* dstbuf) {
    for (int e = blockIdx.x * blockDim.x + threadIdx.x; e < EE;
         e += gridDim.x * blockDim.x) {
        int d = edge_at(dstbuf, e);
        int s = edge_at(srcbuf, e);
        int pos = atomicAdd(&g_cursor[d], 1);
        g_col[g_rowptr[d] + pos] = s;
    }
}

// ------ gather: h = 0.9 * sum_src f(zh[src]) + 0.1 * x0  (zh is fp16) -------
// BNMODE 0: f = identity.  BNMODE 1: f(v) = relu(v * s[c] + t[c]).
template <int BNMODE>
__global__ void gather_k(const __half* __restrict__ zh,
                         const float* __restrict__ x0,
                         float* __restrict__ h) {
    int gw = (blockIdx.x * blockDim.x + threadIdx.x) >> 5;
    if (gw >= NN) return;
    int lane = threadIdx.x & 31;
    float4 s4, t4;
    if (BNMODE) {
        s4 = *(const float4*)(g_bns + lane * 4);
        t4 = *(const float4*)(g_bnt + lane * 4);
    }
    int beg = g_rowptr[gw], end = g_rowptr[gw + 1];
    float4 acc = make_float4(0.f, 0.f, 0.f, 0.f);
    int e = beg;
    // each lane reads 4 fp16 values (8B) of a 256B row
    #define LD4H(v, s) do { \
        uint2 _u = ((const uint2*)(zh + (long)(s) * HH))[lane]; \
        float2 _f01 = __half22float2(*(__half2*)&_u.x); \
        float2 _f23 = __half22float2(*(__half2*)&_u.y); \
        (v).x = _f01.x; (v).y = _f01.y; (v).z = _f23.x; (v).w = _f23.y; } while (0)
    #define XF(v) do { if (BNMODE) { \
        (v).x = fmaxf(fmaf((v).x, s4.x, t4.x), 0.f); \
        (v).y = fmaxf(fmaf((v).y, s4.y, t4.y), 0.f); \
        (v).z = fmaxf(fmaf((v).z, s4.z, t4.z), 0.f); \
        (v).w = fmaxf(fmaf((v).w, s4.w, t4.w), 0.f); } } while (0)
    for (; e + 3 < end; e += 4) {
        int s0 = g_col[e], s1 = g_col[e + 1], s2 = g_col[e + 2], s3 = g_col[e + 3];
        float4 v0, v1, v2, v3;
        LD4H(v0, s0); LD4H(v1, s1); LD4H(v2, s2); LD4H(v3, s3);
        XF(v0); XF(v1); XF(v2); XF(v3);
        acc.x += (v0.x + v1.x) + (v2.x + v3.x);
        acc.y += (v0.y + v1.y) + (v2.y + v3.y);
        acc.z += (v0.z + v1.z) + (v2.z + v3.z);
        acc.w += (v0.w + v1.w) + (v2.w + v3.w);
    }
    for (; e < end; ++e) {
        int s = g_col[e];
        float4 v;
        LD4H(v, s);
        XF(v);
        acc.x += v.x; acc.y += v.y; acc.z += v.z; acc.w += v.w;
    }
    #undef XF
    #undef LD4H
    float4 xv = ((const float4*)(x0 + (long)gw * HH))[lane];
    float4 o;
    const float A1 = 0.9f, A0 = 0.1f;
    o.x = A1 * acc.x + A0 * xv.x;
    o.y = A1 * acc.y + A0 * xv.y;
    o.z = A1 * acc.z + A0 * xv.z;
    o.w = A1 * acc.w + A0 * xv.w;
    ((float4*)(h + (long)gw * HH))[lane] = o;
}

// ---------------- BatchNorm zero + finalize ---------------------------------
__global__ void zero_bn_k() {
    int c = threadIdx.x;
    g_bnsum[c] = 0.f;
    g_bnsq[c] = 0.f;
}

__global__ void finalize_bn_k(const float* __restrict__ gamma,
                              const float* __restrict__ beta) {
    int c = threadIdx.x;
    float invN = 1.0f / (float)NN;
    float m = g_bnsum[c] * invN;
    float var = g_bnsq[c] * invN - m * m;
    float s = rsqrtf(var + 1e-5f) * gamma[c];
    g_bns[c] = s;
    g_bnt[c] = beta[c] - m * s;
}

// ---------------- host orchestration ----------------------------------------
extern "C" void kernel_launch(void* const* d_in, const int* in_sizes, int n_in,
                              void* d_out, int out_size) {
    const float* x     = (const float*)d_in[0];
    const float* W_in  = (const float*)d_in[1];
    const float* b_in  = (const float*)d_in[2];
    const float* convW = (const float*)d_in[3];
    const float* gma   = (const float*)d_in[4];
    const float* bta   = (const float*)d_in[5];
    const float* W_jk  = (const float*)d_in[6];
    const float* b_jk  = (const float*)d_in[7];
    const void*  src   = d_in[8];
    const void*  dst   = d_in[9];
    float* out = (float*)d_out;

    void *px0, *ph, *pzs, *pzh;
    cudaGetSymbolAddress(&px0, g_x0);
    cudaGetSymbolAddress(&ph, g_h);
    cudaGetSymbolAddress(&pzs, g_zs);
    cudaGetSymbolAddress(&pzh, g_zh);
    float* x0   = (float*)px0;
    float* h    = (float*)ph;
    float* zs0  = (float*)pzs;
    float* zs1  = zs0 + (long)NN * HH;
    float* zs2  = zs1 + (long)NN * HH;
    float* zs3  = zs2 + (long)NN * HH;
    __half* zh0 = (__half*)pzh;                 // input-layer output (== x0)
    __half* zh1 = zh0 + (long)NN * HH;          // conv0 output (zs0)
    __half* zh2 = zh1 + (long)NN * HH;          // conv1 output (zs1)
    __half* zh3 = zh2 + (long)NN * HH;          // conv2 output (zs2)
    __half* zh4 = zh3 + (long)NN * HH;          // JK output

    float bl[LL];
    for (int i = 0; i < LL; i++) bl[i] = (float)log(0.5 / (double)(i + 1) + 1.0);

    cudaFuncSetAttribute(gemm_tc_k<0, 0>, cudaFuncAttributeMaxDynamicSharedMemorySize, SM_TOTAL);
    cudaFuncSetAttribute(gemm_tc_k<1, 0>, cudaFuncAttributeMaxDynamicSharedMemorySize, SM_TOTAL);
    cudaFuncSetAttribute(gemm_tc_k<1, 1>, cudaFuncAttributeMaxDynamicSharedMemorySize, SM_TOTAL);
    cudaFuncSetAttribute(gemm_tc_k<2, 0>, cudaFuncAttributeMaxDynamicSharedMemorySize, SM_TOTAL);

    const int GEMM_BLOCKS = (NN + 127) / 128;            // 782
    const int GATHER_BLOCKS = (NN * 32 + 255) / 256;
    const int SCAN_BLOCKS = (NN + 1023) / 1024;          // 98

    // ---- forked side stream: CSR build concurrent with prep_b + input GEMM --
    cudaStream_t s2;
    cudaStreamCreateWithFlags(&s2, cudaStreamNonBlocking);
    cudaEvent_t evFork, evJoin;
    cudaEventCreateWithFlags(&evFork, cudaEventDisableTiming);
    cudaEventCreateWithFlags(&evJoin, cudaEventDisableTiming);

    cudaEventRecord(evFork, 0);
    cudaStreamWaitEvent(s2, evFork, 0);

    zero_csr_k<<<(NN + 255) / 256, 256, 0, s2>>>();
    detect64_k<<<1, 1, 0, s2>>>(src);
    hist_k<<<1024, 256, 0, s2>>>(dst);
    scanA_k<<<SCAN_BLOCKS, 1024, 0, s2>>>();
    scanB_k<<<1, 1, 0, s2>>>(SCAN_BLOCKS);
    scanC_k<<<SCAN_BLOCKS, 1024, 0, s2>>>();
    fill_k<<<1024, 256, 0, s2>>>(src, dst);
    cudaEventRecord(evJoin, s2);

    // main stream: B-tile prep + input GEMM (-> x0 fp32 + fp16 copy)
    prep_b_k<<<10, 256>>>(W_in, convW, W_jk, bl[0], bl[1], bl[2], bl[3], bl[4]);
    gemm_tc_k<0, 0><<<GEMM_BLOCKS, 256, SM_TOTAL>>>(x, 0, 0, 0, b_in, 0, x0, zh0);

    cudaStreamWaitEvent(0, evJoin, 0);

    float* zsbuf[4] = {zs0, zs1, zs2, zs3};
    const __half* gin[LL] = {zh0, zh1, zh2, zh3, zh4};
    __half* chout[LL] = {zh1, zh2, zh3, 0, 0};
    for (int i = 0; i < LL; i++) {
        if (i >= 1 && i <= 3)
            gather_k<1><<<GATHER_BLOCKS, 256>>>(gin[i], x0, h);
        else
            gather_k<0><<<GATHER_BLOCKS, 256>>>(gin[i], x0, h);
        float* Cout = (i < 4) ? zsbuf[i] : out;
        if (i < 3) {
            zero_bn_k<<<1, HH>>>();
            gemm_tc_k<1, 1><<<GEMM_BLOCKS, 256, SM_TOTAL>>>(h, 0, 0, 0, 0, 1 + i,
                                                            Cout, chout[i]);
            finalize_bn_k<<<1, HH>>>(gma + i * HH, bta + i * HH);
        } else {
            gemm_tc_k<1, 0><<<GEMM_BLOCKS, 256, SM_TOTAL>>>(h, 0, 0, 0, 0, 1 + i,
                                                            Cout, chout[i]);
        }
        if (i == 3) {
            // JK output feeds only the layer-4 gather -> fp16 copy only
            gemm_tc_k<2, 0><<<GEMM_BLOCKS, 256, SM_TOTAL>>>(zs0, zs1, zs2, zs3,
                                                            b_jk, 6, 0, zh4);
        }
    }

    cudaEventDestroy(evFork);
    cudaEventDestroy(evJoin);
    cudaStreamDestroy(s2);
    (void)in_sizes; (void)n_in; (void)out_size;
}

// round 12
// speedup vs baseline: 1.7255x; 1.1655x over previous
#include <cuda_runtime.h>
#include <cuda_bf16.h>
#include <cuda_fp16.h>
#include <math.h>
#include <stdint.h>

#define NN 100000
#define EE 1600000
#define HH 128
#define LL 5

// ---------------- device scratch (static; no allocations allowed) ----------
// fp16 activation slots: 0=input-layer out (x0), 1..4=conv0..3 out, 5=JK out
__device__ __align__(16) __half g_zh[6 * NN * HH];
__device__ __align__(16) __half g_h[NN * HH];       // gather output (fp16)
__device__ __align__(16) uint8_t g_Bh[10 * 32768];
__device__ __align__(16) uint8_t g_Bl[10 * 32768];
__device__ int   g_deg[NN];
__device__ int   g_rowptr[NN + 1];
__device__ int   g_cursor[NN];
__device__ int   g_col[EE];
__device__ int   g_is64;
__device__ int   g_part[128];
__device__ int   g_partoff[128];
__device__ float g_bnsum[HH];
__device__ float g_bnsq[HH];
__device__ float g_bns[HH];
__device__ float g_bnt[HH];

// ---------------- helpers ---------------------------------------------------
__device__ __forceinline__ uint32_t smem_u32(const void* p) {
    uint32_t a;
    asm("{ .reg .u64 t; cvta.to.shared.u64 t, %1; cvt.u32.u64 %0, t; }"
        : "=r"(a) : "l"(p));
    return a;
}

static __device__ __forceinline__ uint32_t pack_bf2(float a, float b) {
    __nv_bfloat162 t = __floats2bfloat162_rn(a, b);
    return *(uint32_t*)&t;
}

// XOR-swizzled byte offset inside a (rows x 128) bf16 tile (pitch 256B).
__device__ __forceinline__ int swz(int row, int col) {
    return row * 256 + ((((col >> 3) ^ (row & 7)) & 15) << 4) + ((col & 7) << 1);
}

#define LDMX4(r0, r1, r2, r3, addr) \
    asm volatile("ldmatrix.sync.aligned.m8n8.x4.shared.b16 {%0,%1,%2,%3}, [%4];" \
                 : "=r"(r0), "=r"(r1), "=r"(r2), "=r"(r3) : "r"(addr))

#define MMA16816(c, a, b0, b1) \
    asm volatile( \
        "mma.sync.aligned.m16n8k16.row.col.f32.bf16.bf16.f32 " \
        "{%0,%1,%2,%3}, {%4,%5,%6,%7}, {%8,%9}, {%0,%1,%2,%3};" \
        : "+f"((c)[0]), "+f"((c)[1]), "+f"((c)[2]), "+f"((c)[3]) \
        : "r"((a)[0]), "r"((a)[1]), "r"((a)[2]), "r"((a)[3]), "r"(b0), "r"(b1))

// SMEM: A hi/lo 128x128 bf16 (32KB each) + B hi/lo (32KB each) = 128KB
#define SM_AH 0
#define SM_AL 32768
#define SM_BH 65536
#define SM_BL 98304
#define SM_TOTAL 131072

// ---------------- B-tile preparation (once per launch) ----------------------
__global__ __launch_bounds__(256) void prep_b_k(
    const float* __restrict__ W_in, const float* __restrict__ convW,
    const float* __restrict__ W_jk,
    float b0, float b1, float b2, float b3, float b4) {
    int t = blockIdx.x;
    const float* W;
    float wscale, ident;
    if (t == 0) { W = W_in; wscale = 1.f; ident = 0.f; }
    else if (t <= 5) {
        float blv = (t == 1) ? b0 : (t == 2) ? b1 : (t == 3) ? b2 : (t == 4) ? b3 : b4;
        W = convW + (long)(t - 1) * HH * HH;
        wscale = blv; ident = 1.f - blv;
    } else { W = W_jk + (long)(t - 6) * HH * HH; wscale = 1.f; ident = 0.f; }

    int tid = threadIdx.x;
    int n = tid >> 1;
    int kb = (tid & 1) << 6;
    const float* Wb = W + (long)kb * HH + n;
    uint8_t* bh = g_Bh + (long)t * 32768;
    uint8_t* blo = g_Bl + (long)t * 32768;
    #pragma unroll
    for (int jj = 0; jj < 8; jj++) {
        int k0 = kb + jj * 8;
        float vv[8];
        #pragma unroll
        for (int q = 0; q < 8; q++) {
            float w = Wb[(long)(jj * 8 + q) * HH];
            vv[q] = wscale * w + ((k0 + q) == n ? ident : 0.f);
        }
        uint4 hv, lv;
        uint32_t* hp = &hv.x;
        uint32_t* lp = &lv.x;
        #pragma unroll
        for (int q = 0; q < 4; q++) {
            __nv_bfloat16 ha = __float2bfloat16_rn(vv[q * 2]);
            __nv_bfloat16 hb = __float2bfloat16_rn(vv[q * 2 + 1]);
            hp[q] = pack_bf2(__bfloat162float(ha), __bfloat162float(hb));
            lp[q] = pack_bf2(vv[q * 2] - __bfloat162float(ha),
                             vv[q * 2 + 1] - __bfloat162float(hb));
        }
        int so = swz(n, k0);
        *(uint4*)(bh + so) = hv;
        *(uint4*)(blo + so) = lv;
    }
}

// ---------------- tensor-core GEMM (mma.sync bf16 split, 128x128 tile) ------
// MODE 0/1: single chunk (0 adds bias).  MODE 2: 4 chunks (K=512), +bias.
// STATS 1: atomicAdd per-column sum/sumsq of C into g_bnsum/g_bnsq.
// HALFA 1: A operand(s) are fp16 (hi/lo split is then exact).
// C (fp32) and Ch (fp16) outputs independently nullable.
template <int MODE, int STATS, int HALFA>
__global__ __launch_bounds__(256, 1) void gemm_tc_k(
    const void* __restrict__ A0, const void* __restrict__ A1,
    const void* __restrict__ A2, const void* __restrict__ A3,
    const float* __restrict__ bias, int tbase,
    float* __restrict__ C, __half* __restrict__ Ch) {
    extern __shared__ char smem[];
    uint32_t sb = smem_u32(smem);
    const int tid = threadIdx.x;
    const int wid = tid >> 5, lane = tid & 31;
    const int block_row = blockIdx.x * 128;

    const int wm = (wid & 3) * 32;
    const int wn = (wid >> 2) * 64;
    const int lrow = lane & 7, quad = lane >> 3;

    float acc[2][8][4];
    #pragma unroll
    for (int i = 0; i < 2; i++)
        #pragma unroll
        for (int j = 0; j < 8; j++)
            #pragma unroll
            for (int q = 0; q < 4; q++) acc[i][j][q] = 0.f;

    const int NCH = (MODE == 2) ? 4 : 1;
    for (int c = 0; c < NCH; c++) {
        const void* Ab = (c == 0) ? A0 : (c == 1) ? A1 : (c == 2) ? A2 : A3;
        // ---- A tile fill: fp32/fp16 -> (hi, lo) bf16, swizzled ----
        {
            int row = tid >> 1;
            int cb = (tid & 1) << 6;
            int grow = block_row + row;
            #pragma unroll
            for (int jj = 0; jj < 8; jj++) {
                float4 v0 = make_float4(0.f, 0.f, 0.f, 0.f), v1 = v0;
                if (grow < NN) {
                    if (HALFA) {
                        const uint4* sp = (const uint4*)((const __half*)Ab +
                                            (long)grow * HH + cb);
                        uint4 u = sp[jj];
                        __half2* hp2 = (__half2*)&u;
                        float2 f0 = __half22float2(hp2[0]);
                        float2 f1 = __half22float2(hp2[1]);
                        float2 f2 = __half22float2(hp2[2]);
                        float2 f3 = __half22float2(hp2[3]);
                        v0 = make_float4(f0.x, f0.y, f1.x, f1.y);
                        v1 = make_float4(f2.x, f2.y, f3.x, f3.y);
                    } else {
                        const float4* sp = (const float4*)((const float*)Ab +
                                            (long)grow * HH + cb);
                        v0 = sp[jj * 2];
                        v1 = sp[jj * 2 + 1];
                    }
                }
                __nv_bfloat16 h0 = __float2bfloat16_rn(v0.x);
                __nv_bfloat16 h1 = __float2bfloat16_rn(v0.y);
                __nv_bfloat16 h2 = __float2bfloat16_rn(v0.z);
                __nv_bfloat16 h3 = __float2bfloat16_rn(v0.w);
                __nv_bfloat16 h4 = __float2bfloat16_rn(v1.x);
                __nv_bfloat16 h5 = __float2bfloat16_rn(v1.y);
                __nv_bfloat16 h6 = __float2bfloat16_rn(v1.z);
                __nv_bfloat16 h7 = __float2bfloat16_rn(v1.w);
                uint4 hv, lv;
                hv.x = pack_bf2(__bfloat162float(h0), __bfloat162float(h1));
                hv.y = pack_bf2(__bfloat162float(h2), __bfloat162float(h3));
                hv.z = pack_bf2(__bfloat162float(h4), __bfloat162float(h5));
                hv.w = pack_bf2(__bfloat162float(h6), __bfloat162float(h7));
                lv.x = pack_bf2(v0.x - __bfloat162float(h0), v0.y - __bfloat162float(h1));
                lv.y = pack_bf2(v0.z - __bfloat162float(h2), v0.w - __bfloat162float(h3));
                lv.z = pack_bf2(v1.x - __bfloat162float(h4), v1.y - __bfloat162float(h5));
                lv.w = pack_bf2(v1.z - __bfloat162float(h6), v1.w - __bfloat162float(h7));
                int so = swz(row, cb + jj * 8);
                *(uint4*)(smem + SM_AH + so) = hv;
                *(uint4*)(smem + SM_AL + so) = lv;
            }
        }
        // ---- B tile fill: straight copy of preconverted swizzled images ----
        {
            const uint4* bhsrc = (const uint4*)(g_Bh + (long)(tbase + c) * 32768);
            const uint4* blsrc = (const uint4*)(g_Bl + (long)(tbase + c) * 32768);
            uint4* bhdst = (uint4*)(smem + SM_BH);
            uint4* bldst = (uint4*)(smem + SM_BL);
            #pragma unroll
            for (int s = tid; s < 2048; s += 256) {
                bhdst[s] = bhsrc[s];
                bldst[s] = blsrc[s];
            }
        }
        __syncthreads();

        // ---- compute: 3 split terms (AhBh, AlBh, AhBl) ----
        #pragma unroll
        for (int t = 0; t < 3; t++) {
            const uint32_t Aoff = (t == 1) ? SM_AL : SM_AH;
            const uint32_t Boff = (t == 2) ? SM_BL : SM_BH;
            #pragma unroll
            for (int k16 = 0; k16 < 128; k16 += 16) {
                uint32_t a[2][4];
                #pragma unroll
                for (int mt = 0; mt < 2; mt++) {
                    int row = wm + mt * 16 + (quad & 1) * 8 + lrow;
                    int col = k16 + (quad >> 1) * 8;
                    uint32_t addr = sb + Aoff + swz(row, col);
                    LDMX4(a[mt][0], a[mt][1], a[mt][2], a[mt][3], addr);
                }
                #pragma unroll
                for (int nb = 0; nb < 4; nb++) {
                    int row = wn + nb * 16 + (quad >> 1) * 8 + lrow;
                    int col = k16 + (quad & 1) * 8;
                    uint32_t addr = sb + Boff + swz(row, col);
                    uint32_t b0, b1, b2, b3;
                    LDMX4(b0, b1, b2, b3, addr);
                    #pragma unroll
                    for (int mt = 0; mt < 2; mt++) {
                        MMA16816(acc[mt][nb * 2], a[mt], b0, b1);
                        MMA16816(acc[mt][nb * 2 + 1], a[mt], b2, b3);
                    }
                }
            }
        }
        __syncthreads();
    }

    // ---- epilogue: store fp32 and/or fp16 ----
    #pragma unroll
    for (int mt = 0; mt < 2; mt++) {
        int r0 = block_row + wm + mt * 16 + (lane >> 2);
        int r1 = r0 + 8;
        #pragma unroll
        for (int nt = 0; nt < 8; nt++) {
            int cb = wn + nt * 8 + (lane & 3) * 2;
            float2 p0, p1;
            p0.x = acc[mt][nt][0]; p0.y = acc[mt][nt][1];
            p1.x = acc[mt][nt][2]; p1.y = acc[mt][nt][3];
            if (MODE != 1) {
                float bx = bias[cb], by = bias[cb + 1];
                p0.x += bx; p0.y += by;
                p1.x += bx; p1.y += by;
            }
            if (r0 < NN) {
                if (C)  *(float2*)(C + (long)r0 * HH + cb) = p0;
                if (Ch) *(__half2*)(Ch + (long)r0 * HH + cb) = __floats2half2_rn(p0.x, p0.y);
            }
            if (r1 < NN) {
                if (C)  *(float2*)(C + (long)r1 * HH + cb) = p1;
                if (Ch) *(__half2*)(Ch + (long)r1 * HH + cb) = __floats2half2_rn(p1.x, p1.y);
            }
        }
    }
    // ---- epilogue: fused BN statistics (padded rows contribute exact 0) ----
    if (STATS) {
        #pragma unroll
        for (int nt = 0; nt < 8; nt++) {
            #pragma unroll
            for (int p = 0; p < 2; p++) {
                float a00 = acc[0][nt][p],     a01 = acc[0][nt][2 + p];
                float a10 = acc[1][nt][p],     a11 = acc[1][nt][2 + p];
                float s = (a00 + a01) + (a10 + a11);
                float q = a00 * a00 + a01 * a01 + a10 * a10 + a11 * a11;
                #pragma unroll
                for (int m = 4; m < 32; m <<= 1) {
                    s += __shfl_xor_sync(0xFFFFFFFFu, s, m);
                    q += __shfl_xor_sync(0xFFFFFFFFu, q, m);
                }
                if (lane < 4) {
                    int cb = wn + nt * 8 + lane * 2 + p;
                    atomicAdd(&g_bnsum[cb], s);
                    atomicAdd(&g_bnsq[cb], q);
                }
            }
        }
    }
}

// ---------------- edge-list helpers ----------------------------------------
__device__ __forceinline__ int edge_at(const void* buf, int e) {
    if (g_is64) return (int)((const long long*)buf)[e];
    return ((const int*)buf)[e];
}

__global__ void detect64_k(const void* srcbuf) {
    const unsigned int* p = (const unsigned int*)srcbuf;
    int any = 0;
    for (int i = 1; i < 512; i += 2) any |= (p[i] != 0u);
    g_is64 = any ? 0 : 1;
}

__global__ void zero_csr_k() {
    int i = blockIdx.x * blockDim.x + threadIdx.x;
    if (i < NN) { g_deg[i] = 0; g_cursor[i] = 0; }
}

__global__ void hist_k(const void* dstbuf) {
    for (int e = blockIdx.x * blockDim.x + threadIdx.x; e < EE;
         e += gridDim.x * blockDim.x) {
        atomicAdd(&g_deg[edge_at(dstbuf, e)], 1);
    }
}

__global__ void scanA_k() {
    __shared__ int wt[32];
    int tid = threadIdx.x, lane = tid & 31, wid = tid >> 5;
    int i = blockIdx.x * 1024 + tid;
    int v = (i < NN) ? g_deg[i] : 0;
    int x = v;
    #pragma unroll
    for (int d = 1; d < 32; d <<= 1) {
        int y = __shfl_up_sync(0xFFFFFFFFu, x, d);
        if (lane >= d) x += y;
    }
    if (lane == 31) wt[wid] = x;
    __syncthreads();
    if (wid == 0) {
        int t = wt[lane];
        int tx = t;
        #pragma unroll
        for (int d = 1; d < 32; d <<= 1) {
            int y = __shfl_up_sync(0xFFFFFFFFu, tx, d);
            if (lane >= d) tx += y;
        }
        wt[lane] = tx - t;
    }
    __syncthreads();
    int incl = x + wt[wid];
    if (i < NN) g_rowptr[i] = incl - v;
    if (tid == 1023) g_part[blockIdx.x] = incl;
}

__global__ void scanB_k(int nblk) {
    int s = 0;
    for (int b = 0; b < nblk; b++) { g_partoff[b] = s; s += g_part[b]; }
    g_rowptr[NN] = s;
}

__global__ void scanC_k() {
    int i = blockIdx.x * 1024 + threadIdx.x;
    if (i < NN) g_rowptr[i] += g_partoff[blockIdx.x];
}

__global__ void fill_k(const void* srcbuf, const void* dstbuf) {
    for (int e = blockIdx.x * blockDim.x + threadIdx.x; e < EE;
         e += gridDim.x * blockDim.x) {
        int d = edge_at(dstbuf, e);
        int s = edge_at(srcbuf, e);
        int pos = atomicAdd(&g_cursor[d], 1);
        g_col[g_rowptr[d] + pos] = s;
    }
}

// ------ gather: h = 0.9 * sum_src f(zh[src]) + 0.1 * x0h   (all fp16 I/O) ---
// BNMODE 0: f = identity.  BNMODE 1: f(v) = relu(v * s[c] + t[c]).
template <int BNMODE>
__global__ void gather_k(const __half* __restrict__ zh,
                         const __half* __restrict__ x0h,
                         __half* __restrict__ h) {
    int gw = (blockIdx.x * blockDim.x + threadIdx.x) >> 5;
    if (gw >= NN) return;
    int lane = threadIdx.x & 31;
    float4 s4, t4;
    if (BNMODE) {
        s4 = *(const float4*)(g_bns + lane * 4);
        t4 = *(const float4*)(g_bnt + lane * 4);
    }
    int beg = g_rowptr[gw], end = g_rowptr[gw + 1];
    float4 acc = make_float4(0.f, 0.f, 0.f, 0.f);
    int e = beg;
    #define LD4H(v, p, s) do { \
        uint2 _u = ((const uint2*)((p) + (long)(s) * HH))[lane]; \
        float2 _f01 = __half22float2(*(__half2*)&_u.x); \
        float2 _f23 = __half22float2(*(__half2*)&_u.y); \
        (v).x = _f01.x; (v).y = _f01.y; (v).z = _f23.x; (v).w = _f23.y; } while (0)
    #define XF(v) do { if (BNMODE) { \
        (v).x = fmaxf(fmaf((v).x, s4.x, t4.x), 0.f); \
        (v).y = fmaxf(fmaf((v).y, s4.y, t4.y), 0.f); \
        (v).z = fmaxf(fmaf((v).z, s4.z, t4.z), 0.f); \
        (v).w = fmaxf(fmaf((v).w, s4.w, t4.w), 0.f); } } while (0)
    for (; e + 3 < end; e += 4) {
        int s0 = g_col[e], s1 = g_col[e + 1], s2 = g_col[e + 2], s3 = g_col[e + 3];
        float4 v0, v1, v2, v3;
        LD4H(v0, zh, s0); LD4H(v1, zh, s1); LD4H(v2, zh, s2); LD4H(v3, zh, s3);
        XF(v0); XF(v1); XF(v2); XF(v3);
        acc.x += (v0.x + v1.x) + (v2.x + v3.x);
        acc.y += (v0.y + v1.y) + (v2.y + v3.y);
        acc.z += (v0.z + v1.z) + (v2.z + v3.z);
        acc.w += (v0.w + v1.w) + (v2.w + v3.w);
    }
    for (; e < end; ++e) {
        int s = g_col[e];
        float4 v;
        LD4H(v, zh, s);
        XF(v);
        acc.x += v.x; acc.y += v.y; acc.z += v.z; acc.w += v.w;
    }
    float4 xv;
    LD4H(xv, x0h, gw);
    #undef XF
    #undef LD4H
    const float A1 = 0.9f, A0 = 0.1f;
    float ox = A1 * acc.x + A0 * xv.x;
    float oy = A1 * acc.y + A0 * xv.y;
    float oz = A1 * acc.z + A0 * xv.z;
    float ow = A1 * acc.w + A0 * xv.w;
    uint2 o;
    *(__half2*)&o.x = __floats2half2_rn(ox, oy);
    *(__half2*)&o.y = __floats2half2_rn(oz, ow);
    ((uint2*)(h + (long)gw * HH))[lane] = o;
}

// ---------------- BatchNorm zero + finalize ---------------------------------
__global__ void zero_bn_k() {
    int c = threadIdx.x;
    g_bnsum[c] = 0.f;
    g_bnsq[c] = 0.f;
}

__global__ void finalize_bn_k(const float* __restrict__ gamma,
                              const float* __restrict__ beta) {
    int c = threadIdx.x;
    float invN = 1.0f / (float)NN;
    float m = g_bnsum[c] * invN;
    float var = g_bnsq[c] * invN - m * m;
    float s = rsqrtf(var + 1e-5f) * gamma[c];
    g_bns[c] = s;
    g_bnt[c] = beta[c] - m * s;
}

// ---------------- host orchestration ----------------------------------------
extern "C" void kernel_launch(void* const* d_in, const int* in_sizes, int n_in,
                              void* d_out, int out_size) {
    const float* x     = (const float*)d_in[0];
    const float* W_in  = (const float*)d_in[1];
    const float* b_in  = (const float*)d_in[2];
    const float* convW = (const float*)d_in[3];
    const float* gma   = (const float*)d_in[4];
    const float* bta   = (const float*)d_in[5];
    const float* W_jk  = (const float*)d_in[6];
    const float* b_jk  = (const float*)d_in[7];
    const void*  src   = d_in[8];
    const void*  dst   = d_in[9];
    float* out = (float*)d_out;

    void *ph, *pzh;
    cudaGetSymbolAddress(&ph, g_h);
    cudaGetSymbolAddress(&pzh, g_zh);
    __half* h   = (__half*)ph;
    __half* zh0 = (__half*)pzh;                 // input-layer out (residual)
    __half* zh1 = zh0 + (long)NN * HH;          // conv0 out
    __half* zh2 = zh1 + (long)NN * HH;          // conv1 out
    __half* zh3 = zh2 + (long)NN * HH;          // conv2 out
    __half* zh4 = zh3 + (long)NN * HH;          // conv3 out
    __half* zh5 = zh4 + (long)NN * HH;          // JK out

    float bl[LL];
    for (int i = 0; i < LL; i++) bl[i] = (float)log(0.5 / (double)(i + 1) + 1.0);

    cudaFuncSetAttribute(gemm_tc_k<0, 0, 0>, cudaFuncAttributeMaxDynamicSharedMemorySize, SM_TOTAL);
    cudaFuncSetAttribute(gemm_tc_k<1, 0, 1>, cudaFuncAttributeMaxDynamicSharedMemorySize, SM_TOTAL);
    cudaFuncSetAttribute(gemm_tc_k<1, 1, 1>, cudaFuncAttributeMaxDynamicSharedMemorySize, SM_TOTAL);
    cudaFuncSetAttribute(gemm_tc_k<2, 0, 1>, cudaFuncAttributeMaxDynamicSharedMemorySize, SM_TOTAL);

    const int GEMM_BLOCKS = (NN + 127) / 128;            // 782
    const int GATHER_BLOCKS = (NN * 32 + 255) / 256;
    const int SCAN_BLOCKS = (NN + 1023) / 1024;          // 98

    // ---- forked side stream: CSR build concurrent with prep_b + input GEMM --
    cudaStream_t s2;
    cudaStreamCreateWithFlags(&s2, cudaStreamNonBlocking);
    cudaEvent_t evFork, evJoin;
    cudaEventCreateWithFlags(&evFork, cudaEventDisableTiming);
    cudaEventCreateWithFlags(&evJoin, cudaEventDisableTiming);

    cudaEventRecord(evFork, 0);
    cudaStreamWaitEvent(s2, evFork, 0);

    zero_csr_k<<<(NN + 255) / 256, 256, 0, s2>>>();
    detect64_k<<<1, 1, 0, s2>>>(src);
    hist_k<<<1024, 256, 0, s2>>>(dst);
    scanA_k<<<SCAN_BLOCKS, 1024, 0, s2>>>();
    scanB_k<<<1, 1, 0, s2>>>(SCAN_BLOCKS);
    scanC_k<<<SCAN_BLOCKS, 1024, 0, s2>>>();
    fill_k<<<1024, 256, 0, s2>>>(src, dst);
    cudaEventRecord(evJoin, s2);

    // main stream: B-tile prep + input GEMM (fp32 A, fp16 out only)
    prep_b_k<<<10, 256>>>(W_in, convW, W_jk, bl[0], bl[1], bl[2], bl[3], bl[4]);
    gemm_tc_k<0, 0, 0><<<GEMM_BLOCKS, 256, SM_TOTAL>>>(x, 0, 0, 0, b_in, 0, 0, zh0);

    cudaStreamWaitEvent(0, evJoin, 0);

    const __half* gin[LL]  = {zh0, zh1, zh2, zh3, zh5};  // gather sources
    __half* chout[LL]      = {zh1, zh2, zh3, zh4, 0};    // conv fp16 outputs
    for (int i = 0; i < LL; i++) {
        if (i >= 1 && i <= 3)
            gather_k<1><<<GATHER_BLOCKS, 256>>>(gin[i], zh0, h);
        else
            gather_k<0><<<GATHER_BLOCKS, 256>>>(gin[i], zh0, h);
        float* Cout = (i == 4) ? out : 0;
        if (i < 3) {
            zero_bn_k<<<1, HH>>>();
            gemm_tc_k<1, 1, 1><<<GEMM_BLOCKS, 256, SM_TOTAL>>>(h, 0, 0, 0, 0, 1 + i,
                                                               Cout, chout[i]);
            finalize_bn_k<<<1, HH>>>(gma + i * HH, bta + i * HH);
        } else {
            gemm_tc_k<1, 0, 1><<<GEMM_BLOCKS, 256, SM_TOTAL>>>(h, 0, 0, 0, 0, 1 + i,
                                                               Cout, chout[i]);
        }
        if (i == 3) {
            // JK: A = conv0..3 fp16 outputs, writes fp16 only (feeds gather 4)
            gemm_tc_k<2, 0, 1><<<GEMM_BLOCKS, 256, SM_TOTAL>>>(zh1, zh2, zh3, zh4,
                                                               b_jk, 6, 0, zh5);
        }
    }

    cudaEventDestroy(evFork);
    cudaEventDestroy(evJoin);
    cudaStreamDestroy(s2);
    (void)in_sizes; (void)n_in; (void)out_size;
}

// round 13
// speedup vs baseline: 1.9433x; 1.1262x over previous
#include <cuda_runtime.h>
#include <cuda_fp16.h>
#include <math.h>
#include <stdint.h>

#define NN 100000
#define EE 1600000
#define HH 128
#define LL 5

// ---------------- device scratch (static; no allocations allowed) ----------
// fp16 activation slots: 0=input-layer out (x0), 1..4=conv0..3 out, 5=JK out
__device__ __align__(16) __half g_zh[6 * NN * HH];
__device__ __align__(16) __half g_h[NN * HH];       // gather out / xh scratch
__device__ __align__(16) uint8_t g_Bh[10 * 32768];  // Wh fp16 swizzled tiles
__device__ __align__(16) uint8_t g_Bl[10 * 32768];  // Wl fp16 swizzled tiles
__device__ int   g_deg[NN];
__device__ int   g_rowptr[NN + 1];
__device__ int   g_cursor[NN];
__device__ int   g_col[EE];
__device__ int   g_is64;
__device__ int   g_part[128];
__device__ int   g_partoff[128];
__device__ float g_bnsum[HH];
__device__ float g_bnsq[HH];
__device__ float g_bns[HH];
__device__ float g_bnt[HH];

// ---------------- helpers ---------------------------------------------------
__device__ __forceinline__ uint32_t smem_u32(const void* p) {
    uint32_t a;
    asm("{ .reg .u64 t; cvta.to.shared.u64 t, %1; cvt.u32.u64 %0, t; }"
        : "=r"(a) : "l"(p));
    return a;
}

static __device__ __forceinline__ uint32_t pack_h2(float a, float b) {
    __half2 t = __floats2half2_rn(a, b);
    return *(uint32_t*)&t;
}

// XOR-swizzled byte offset inside a (rows x 128) fp16 tile (pitch 256B).
__device__ __forceinline__ int swz(int row, int col) {
    return row * 256 + ((((col >> 3) ^ (row & 7)) & 15) << 4) + ((col & 7) << 1);
}

#define LDMX4(r0, r1, r2, r3, addr) \
    asm volatile("ldmatrix.sync.aligned.m8n8.x4.shared.b16 {%0,%1,%2,%3}, [%4];" \
                 : "=r"(r0), "=r"(r1), "=r"(r2), "=r"(r3) : "r"(addr))

#define MMA16816H(c, a, b0, b1) \
    asm volatile( \
        "mma.sync.aligned.m16n8k16.row.col.f32.f16.f16.f32 " \
        "{%0,%1,%2,%3}, {%4,%5,%6,%7}, {%8,%9}, {%0,%1,%2,%3};" \
        : "+f"((c)[0]), "+f"((c)[1]), "+f"((c)[2]), "+f"((c)[3]) \
        : "r"((a)[0]), "r"((a)[1]), "r"((a)[2]), "r"((a)[3]), "r"(b0), "r"(b1))

// SMEM: A fp16 128x128 (32KB) + B hi/lo fp16 (32KB each) = 96KB -> 2 CTA/SM
#define SM_A  0
#define SM_BH 32768
#define SM_BL 65536
#define SM_TOTAL 98304

// ---------------- x -> fp16 convert (input layer A) --------------------------
__global__ void cvt_x_k(const float* __restrict__ x, __half* __restrict__ xh) {
    int i = blockIdx.x * blockDim.x + threadIdx.x;
    if (i < NN * HH / 4) {
        float4 v = ((const float4*)x)[i];
        uint2 o;
        o.x = pack_h2(v.x, v.y);
        o.y = pack_h2(v.z, v.w);
        ((uint2*)xh)[i] = o;
    }
}

// ---------------- B-tile preparation (once per launch) ----------------------
// Wmma[n][k] = wscale*W[k*H+n] (+ident diag), split into fp16 hi + fp16 lo.
__global__ __launch_bounds__(256) void prep_b_k(
    const float* __restrict__ W_in, const float* __restrict__ convW,
    const float* __restrict__ W_jk,
    float b0, float b1, float b2, float b3, float b4) {
    int t = blockIdx.x;
    const float* W;
    float wscale, ident;
    if (t == 0) { W = W_in; wscale = 1.f; ident = 0.f; }
    else if (t <= 5) {
        float blv = (t == 1) ? b0 : (t == 2) ? b1 : (t == 3) ? b2 : (t == 4) ? b3 : b4;
        W = convW + (long)(t - 1) * HH * HH;
        wscale = blv; ident = 1.f - blv;
    } else { W = W_jk + (long)(t - 6) * HH * HH; wscale = 1.f; ident = 0.f; }

    int tid = threadIdx.x;
    int n = tid >> 1;
    int kb = (tid & 1) << 6;
    const float* Wb = W + (long)kb * HH + n;
    uint8_t* bh = g_Bh + (long)t * 32768;
    uint8_t* blo = g_Bl + (long)t * 32768;
    #pragma unroll
    for (int jj = 0; jj < 8; jj++) {
        int k0 = kb + jj * 8;
        float vv[8];
        #pragma unroll
        for (int q = 0; q < 8; q++) {
            float w = Wb[(long)(jj * 8 + q) * HH];
            vv[q] = wscale * w + ((k0 + q) == n ? ident : 0.f);
        }
        uint4 hv, lv;
        uint32_t* hp = &hv.x;
        uint32_t* lp = &lv.x;
        #pragma unroll
        for (int q = 0; q < 4; q++) {
            __half ha = __float2half_rn(vv[q * 2]);
            __half hb = __float2half_rn(vv[q * 2 + 1]);
            hp[q] = pack_h2(__half2float(ha), __half2float(hb));
            lp[q] = pack_h2(vv[q * 2] - __half2float(ha),
                            vv[q * 2 + 1] - __half2float(hb));
        }
        int so = swz(n, k0);
        *(uint4*)(bh + so) = hv;
        *(uint4*)(blo + so) = lv;
    }
}

// ---------------- tensor-core GEMM (fp16 A exact, 2-term W split) -----------
// MODE 0: single chunk +bias.  MODE 1: plain.  MODE 2: 4 chunks (K=512) +bias.
// STATS 1: atomicAdd per-column sum/sumsq of C into g_bnsum/g_bnsq.
// C (fp32) and Ch (fp16) outputs independently nullable.
template <int MODE, int STATS>
__global__ __launch_bounds__(256, 2) void gemm_tc_k(
    const __half* __restrict__ A0, const __half* __restrict__ A1,
    const __half* __restrict__ A2, const __half* __restrict__ A3,
    const float* __restrict__ bias, int tbase,
    float* __restrict__ C, __half* __restrict__ Ch) {
    extern __shared__ char smem[];
    uint32_t sb = smem_u32(smem);
    const int tid = threadIdx.x;
    const int wid = tid >> 5, lane = tid & 31;
    const int block_row = blockIdx.x * 128;

    const int wm = (wid & 3) * 32;
    const int wn = (wid >> 2) * 64;
    const int lrow = lane & 7, quad = lane >> 3;

    float acc[2][8][4];
    #pragma unroll
    for (int i = 0; i < 2; i++)
        #pragma unroll
        for (int j = 0; j < 8; j++)
            #pragma unroll
            for (int q = 0; q < 4; q++) acc[i][j][q] = 0.f;

    const int NCH = (MODE == 2) ? 4 : 1;
    for (int c = 0; c < NCH; c++) {
        const __half* Ab = (c == 0) ? A0 : (c == 1) ? A1 : (c == 2) ? A2 : A3;
        // ---- A tile fill: straight fp16 byte copy into swizzled smem ----
        {
            int row = tid >> 1;
            int cb = (tid & 1) << 6;
            int grow = block_row + row;
            const uint4* sp = (const uint4*)(Ab + (long)grow * HH + cb);
            #pragma unroll
            for (int jj = 0; jj < 8; jj++) {
                uint4 u = make_uint4(0u, 0u, 0u, 0u);
                if (grow < NN) u = sp[jj];
                *(uint4*)(smem + SM_A + swz(row, cb + jj * 8)) = u;
            }
        }
        // ---- B tile fill: straight copy of preconverted swizzled images ----
        {
            const uint4* bhsrc = (const uint4*)(g_Bh + (long)(tbase + c) * 32768);
            const uint4* blsrc = (const uint4*)(g_Bl + (long)(tbase + c) * 32768);
            uint4* bhdst = (uint4*)(smem + SM_BH);
            uint4* bldst = (uint4*)(smem + SM_BL);
            #pragma unroll
            for (int s = tid; s < 2048; s += 256) {
                bhdst[s] = bhsrc[s];
                bldst[s] = blsrc[s];
            }
        }
        __syncthreads();

        // ---- compute: 2 terms (A.Wh, A.Wl) ----
        #pragma unroll
        for (int t = 0; t < 2; t++) {
            const uint32_t Boff = (t == 0) ? SM_BH : SM_BL;
            #pragma unroll
            for (int k16 = 0; k16 < 128; k16 += 16) {
                uint32_t a[2][4];
                #pragma unroll
                for (int mt = 0; mt < 2; mt++) {
                    int row = wm + mt * 16 + (quad & 1) * 8 + lrow;
                    int col = k16 + (quad >> 1) * 8;
                    uint32_t addr = sb + SM_A + swz(row, col);
                    LDMX4(a[mt][0], a[mt][1], a[mt][2], a[mt][3], addr);
                }
                #pragma unroll
                for (int nb = 0; nb < 4; nb++) {
                    int row = wn + nb * 16 + (quad >> 1) * 8 + lrow;
                    int col = k16 + (quad & 1) * 8;
                    uint32_t addr = sb + Boff + swz(row, col);
                    uint32_t b0, b1, b2, b3;
                    LDMX4(b0, b1, b2, b3, addr);
                    #pragma unroll
                    for (int mt = 0; mt < 2; mt++) {
                        MMA16816H(acc[mt][nb * 2], a[mt], b0, b1);
                        MMA16816H(acc[mt][nb * 2 + 1], a[mt], b2, b3);
                    }
                }
            }
        }
        __syncthreads();
    }

    // ---- epilogue: store fp32 and/or fp16 ----
    #pragma unroll
    for (int mt = 0; mt < 2; mt++) {
        int r0 = block_row + wm + mt * 16 + (lane >> 2);
        int r1 = r0 + 8;
        #pragma unroll
        for (int nt = 0; nt < 8; nt++) {
            int cb = wn + nt * 8 + (lane & 3) * 2;
            float2 p0, p1;
            p0.x = acc[mt][nt][0]; p0.y = acc[mt][nt][1];
            p1.x = acc[mt][nt][2]; p1.y = acc[mt][nt][3];
            if (MODE != 1) {
                float bx = bias[cb], by = bias[cb + 1];
                p0.x += bx; p0.y += by;
                p1.x += bx; p1.y += by;
            }
            if (r0 < NN) {
                if (C)  *(float2*)(C + (long)r0 * HH + cb) = p0;
                if (Ch) *(uint32_t*)(Ch + (long)r0 * HH + cb) = pack_h2(p0.x, p0.y);
            }
            if (r1 < NN) {
                if (C)  *(float2*)(C + (long)r1 * HH + cb) = p1;
                if (Ch) *(uint32_t*)(Ch + (long)r1 * HH + cb) = pack_h2(p1.x, p1.y);
            }
        }
    }
    // ---- epilogue: fused BN statistics (padded rows contribute exact 0) ----
    if (STATS) {
        #pragma unroll
        for (int nt = 0; nt < 8; nt++) {
            #pragma unroll
            for (int p = 0; p < 2; p++) {
                float a00 = acc[0][nt][p],     a01 = acc[0][nt][2 + p];
                float a10 = acc[1][nt][p],     a11 = acc[1][nt][2 + p];
                float s = (a00 + a01) + (a10 + a11);
                float q = a00 * a00 + a01 * a01 + a10 * a10 + a11 * a11;
                #pragma unroll
                for (int m = 4; m < 32; m <<= 1) {
                    s += __shfl_xor_sync(0xFFFFFFFFu, s, m);
                    q += __shfl_xor_sync(0xFFFFFFFFu, q, m);
                }
                if (lane < 4) {
                    int cb = wn + nt * 8 + lane * 2 + p;
                    atomicAdd(&g_bnsum[cb], s);
                    atomicAdd(&g_bnsq[cb], q);
                }
            }
        }
    }
}

// ---------------- edge-list helpers ----------------------------------------
__device__ __forceinline__ int edge_at(const void* buf, int e) {
    if (g_is64) return (int)((const long long*)buf)[e];
    return ((const int*)buf)[e];
}

__global__ void detect64_k(const void* srcbuf) {
    const unsigned int* p = (const unsigned int*)srcbuf;
    int any = 0;
    for (int i = 1; i < 512; i += 2) any |= (p[i] != 0u);
    g_is64 = any ? 0 : 1;
}

__global__ void zero_csr_k() {
    int i = blockIdx.x * blockDim.x + threadIdx.x;
    if (i < NN) { g_deg[i] = 0; g_cursor[i] = 0; }
}

__global__ void hist_k(const void* dstbuf) {
    for (int e = blockIdx.x * blockDim.x + threadIdx.x; e < EE;
         e += gridDim.x * blockDim.x) {
        atomicAdd(&g_deg[edge_at(dstbuf, e)], 1);
    }
}

__global__ void scanA_k() {
    __shared__ int wt[32];
    int tid = threadIdx.x, lane = tid & 31, wid = tid >> 5;
    int i = blockIdx.x * 1024 + tid;
    int v = (i < NN) ? g_deg[i] : 0;
    int x = v;
    #pragma unroll
    for (int d = 1; d < 32; d <<= 1) {
        int y = __shfl_up_sync(0xFFFFFFFFu, x, d);
        if (lane >= d) x += y;
    }
    if (lane == 31) wt[wid] = x;
    __syncthreads();
    if (wid == 0) {
        int t = wt[lane];
        int tx = t;
        #pragma unroll
        for (int d = 1; d < 32; d <<= 1) {
            int y = __shfl_up_sync(0xFFFFFFFFu, tx, d);
            if (lane >= d) tx += y;
        }
        wt[lane] = tx - t;
    }
    __syncthreads();
    int incl = x + wt[wid];
    if (i < NN) g_rowptr[i] = incl - v;
    if (tid == 1023) g_part[blockIdx.x] = incl;
}

__global__ void scanB_k(int nblk) {
    int s = 0;
    for (int b = 0; b < nblk; b++) { g_partoff[b] = s; s += g_part[b]; }
    g_rowptr[NN] = s;
}

__global__ void scanC_k() {
    int i = blockIdx.x * 1024 + threadIdx.x;
    if (i < NN) g_rowptr[i] += g_partoff[blockIdx.x];
}

__global__ void fill_k(const void* srcbuf, const void* dstbuf) {
    for (int e = blockIdx.x * blockDim.x + threadIdx.x; e < EE;
         e += gridDim.x * blockDim.x) {
        int d = edge_at(dstbuf, e);
        int s = edge_at(srcbuf, e);
        int pos = atomicAdd(&g_cursor[d], 1);
        g_col[g_rowptr[d] + pos] = s;
    }
}

// ------ gather: h = 0.9 * sum_src f(zh[src]) + 0.1 * x0h   (all fp16 I/O) ---
// BNMODE 0: f = identity.  BNMODE 1: f(v) = relu(v * s[c] + t[c]).
template <int BNMODE>
__global__ void gather_k(const __half* __restrict__ zh,
                         const __half* __restrict__ x0h,
                         __half* __restrict__ h) {
    int gw = (blockIdx.x * blockDim.x + threadIdx.x) >> 5;
    if (gw >= NN) return;
    int lane = threadIdx.x & 31;
    float4 s4, t4;
    if (BNMODE) {
        s4 = *(const float4*)(g_bns + lane * 4);
        t4 = *(const float4*)(g_bnt + lane * 4);
    }
    int beg = g_rowptr[gw], end = g_rowptr[gw + 1];
    float4 acc = make_float4(0.f, 0.f, 0.f, 0.f);
    int e = beg;
    #define LD4H(v, p, s) do { \
        uint2 _u = ((const uint2*)((p) + (long)(s) * HH))[lane]; \
        float2 _f01 = __half22float2(*(__half2*)&_u.x); \
        float2 _f23 = __half22float2(*(__half2*)&_u.y); \
        (v).x = _f01.x; (v).y = _f01.y; (v).z = _f23.x; (v).w = _f23.y; } while (0)
    #define XF(v) do { if (BNMODE) { \
        (v).x = fmaxf(fmaf((v).x, s4.x, t4.x), 0.f); \
        (v).y = fmaxf(fmaf((v).y, s4.y, t4.y), 0.f); \
        (v).z = fmaxf(fmaf((v).z, s4.z, t4.z), 0.f); \
        (v).w = fmaxf(fmaf((v).w, s4.w, t4.w), 0.f); } } while (0)
    for (; e + 3 < end; e += 4) {
        int s0 = g_col[e], s1 = g_col[e + 1], s2 = g_col[e + 2], s3 = g_col[e + 3];
        float4 v0, v1, v2, v3;
        LD4H(v0, zh, s0); LD4H(v1, zh, s1); LD4H(v2, zh, s2); LD4H(v3, zh, s3);
        XF(v0); XF(v1); XF(v2); XF(v3);
        acc.x += (v0.x + v1.x) + (v2.x + v3.x);
        acc.y += (v0.y + v1.y) + (v2.y + v3.y);
        acc.z += (v0.z + v1.z) + (v2.z + v3.z);
        acc.w += (v0.w + v1.w) + (v2.w + v3.w);
    }
    for (; e < end; ++e) {
        int s = g_col[e];
        float4 v;
        LD4H(v, zh, s);
        XF(v);
        acc.x += v.x; acc.y += v.y; acc.z += v.z; acc.w += v.w;
    }
    float4 xv;
    LD4H(xv, x0h, gw);
    #undef XF
    #undef LD4H
    const float A1 = 0.9f, A0 = 0.1f;
    float ox = A1 * acc.x + A0 * xv.x;
    float oy = A1 * acc.y + A0 * xv.y;
    float oz = A1 * acc.z + A0 * xv.z;
    float ow = A1 * acc.w + A0 * xv.w;
    uint2 o;
    o.x = pack_h2(ox, oy);
    o.y = pack_h2(oz, ow);
    ((uint2*)(h + (long)gw * HH))[lane] = o;
}

// ---------------- BatchNorm zero + finalize ---------------------------------
__global__ void zero_bn_k() {
    int c = threadIdx.x;
    g_bnsum[c] = 0.f;
    g_bnsq[c] = 0.f;
}

__global__ void finalize_bn_k(const float* __restrict__ gamma,
                              const float* __restrict__ beta) {
    int c = threadIdx.x;
    float invN = 1.0f / (float)NN;
    float m = g_bnsum[c] * invN;
    float var = g_bnsq[c] * invN - m * m;
    float s = rsqrtf(var + 1e-5f) * gamma[c];
    g_bns[c] = s;
    g_bnt[c] = beta[c] - m * s;
}

// ---------------- host orchestration ----------------------------------------
extern "C" void kernel_launch(void* const* d_in, const int* in_sizes, int n_in,
                              void* d_out, int out_size) {
    const float* x     = (const float*)d_in[0];
    const float* W_in  = (const float*)d_in[1];
    const float* b_in  = (const float*)d_in[2];
    const float* convW = (const float*)d_in[3];
    const float* gma   = (const float*)d_in[4];
    const float* bta   = (const float*)d_in[5];
    const float* W_jk  = (const float*)d_in[6];
    const float* b_jk  = (const float*)d_in[7];
    const void*  src   = d_in[8];
    const void*  dst   = d_in[9];
    float* out = (float*)d_out;

    void *ph, *pzh;
    cudaGetSymbolAddress(&ph, g_h);
    cudaGetSymbolAddress(&pzh, g_zh);
    __half* h   = (__half*)ph;
    __half* zh0 = (__half*)pzh;                 // input-layer out (residual)
    __half* zh1 = zh0 + (long)NN * HH;          // conv0 out
    __half* zh2 = zh1 + (long)NN * HH;          // conv1 out
    __half* zh3 = zh2 + (long)NN * HH;          // conv2 out
    __half* zh4 = zh3 + (long)NN * HH;          // conv3 out
    __half* zh5 = zh4 + (long)NN * HH;          // JK out

    float bl[LL];
    for (int i = 0; i < LL; i++) bl[i] = (float)log(0.5 / (double)(i + 1) + 1.0);

    cudaFuncSetAttribute(gemm_tc_k<0, 0>, cudaFuncAttributeMaxDynamicSharedMemorySize, SM_TOTAL);
    cudaFuncSetAttribute(gemm_tc_k<1, 0>, cudaFuncAttributeMaxDynamicSharedMemorySize, SM_TOTAL);
    cudaFuncSetAttribute(gemm_tc_k<1, 1>, cudaFuncAttributeMaxDynamicSharedMemorySize, SM_TOTAL);
    cudaFuncSetAttribute(gemm_tc_k<2, 0>, cudaFuncAttributeMaxDynamicSharedMemorySize, SM_TOTAL);

    const int GEMM_BLOCKS = (NN + 127) / 128;            // 782
    const int GATHER_BLOCKS = (NN * 32 + 255) / 256;
    const int SCAN_BLOCKS = (NN + 1023) / 1024;          // 98

    // ---- forked side stream: CSR build concurrent with prep + input GEMM ----
    cudaStream_t s2;
    cudaStreamCreateWithFlags(&s2, cudaStreamNonBlocking);
    cudaEvent_t evFork, evJoin;
    cudaEventCreateWithFlags(&evFork, cudaEventDisableTiming);
    cudaEventCreateWithFlags(&evJoin, cudaEventDisableTiming);

    cudaEventRecord(evFork, 0);
    cudaStreamWaitEvent(s2, evFork, 0);

    zero_csr_k<<<(NN + 255) / 256, 256, 0, s2>>>();
    detect64_k<<<1, 1, 0, s2>>>(src);
    hist_k<<<1024, 256, 0, s2>>>(dst);
    scanA_k<<<SCAN_BLOCKS, 1024, 0, s2>>>();
    scanB_k<<<1, 1, 0, s2>>>(SCAN_BLOCKS);
    scanC_k<<<SCAN_BLOCKS, 1024, 0, s2>>>();
    fill_k<<<1024, 256, 0, s2>>>(src, dst);
    cudaEventRecord(evJoin, s2);

    // main stream: convert x -> fp16 (g_h scratch), B prep, input GEMM
    cvt_x_k<<<(NN * HH / 4 + 255) / 256, 256>>>(x, h);
    prep_b_k<<<10, 256>>>(W_in, convW, W_jk, bl[0], bl[1], bl[2], bl[3], bl[4]);
    gemm_tc_k<0, 0><<<GEMM_BLOCKS, 256, SM_TOTAL>>>(h, 0, 0, 0, b_in, 0, 0, zh0);

    cudaStreamWaitEvent(0, evJoin, 0);

    const __half* gin[LL]  = {zh0, zh1, zh2, zh3, zh5};  // gather sources
    __half* chout[LL]      = {zh1, zh2, zh3, zh4, 0};    // conv fp16 outputs
    for (int i = 0; i < LL; i++) {
        if (i >= 1 && i <= 3)
            gather_k<1><<<GATHER_BLOCKS, 256>>>(gin[i], zh0, h);
        else
            gather_k<0><<<GATHER_BLOCKS, 256>>>(gin[i], zh0, h);
        float* Cout = (i == 4) ? out : 0;
        if (i < 3) {
            zero_bn_k<<<1, HH>>>();
            gemm_tc_k<1, 1><<<GEMM_BLOCKS, 256, SM_TOTAL>>>(h, 0, 0, 0, 0, 1 + i,
                                                            Cout, chout[i]);
            finalize_bn_k<<<1, HH>>>(gma + i * HH, bta + i * HH);
        } else {
            gemm_tc_k<1, 0><<<GEMM_BLOCKS, 256, SM_TOTAL>>>(h, 0, 0, 0, 0, 1 + i,
                                                            Cout, chout[i]);
        }
        if (i == 3) {
            // JK: A = conv0..3 fp16 outputs, writes fp16 only (feeds gather 4)
            gemm_tc_k<2, 0><<<GEMM_BLOCKS, 256, SM_TOTAL>>>(zh1, zh2, zh3, zh4,
                                                            b_jk, 6, 0, zh5);
        }
    }

    cudaEventDestroy(evFork);
    cudaEventDestroy(evJoin);
    cudaStreamDestroy(s2);
    (void)in_sizes; (void)n_in; (void)out_size;
}

// round 14
// speedup vs baseline: 2.2906x; 1.1787x over previous
#include <cuda_runtime.h>
#include <cuda_fp16.h>
#include <math.h>
#include <stdint.h>

#define NN 100000
#define EE 1600000
#define HH 128
#define LL 5

// ---------------- device scratch (static; no allocations allowed) ----------
// fp16 activation slots: 0=input-layer out (x0), 1..4=conv0..3 out, 5=JK out
__device__ __align__(16) __half g_zh[6 * NN * HH];
__device__ __align__(16) __half g_h[NN * HH];       // gather out / xh scratch
__device__ __align__(16) uint8_t g_B[10 * 32768];   // fp16 W tiles (swizzled)
__device__ int   g_deg[NN];
__device__ int   g_rowptr[NN + 1];
__device__ int   g_cursor[NN];
__device__ int   g_col[EE];
__device__ int   g_is64;
__device__ int   g_part[128];
__device__ int   g_partoff[128];
__device__ float g_bnsum[HH];
__device__ float g_bnsq[HH];
__device__ float g_bns[HH];
__device__ float g_bnt[HH];

// ---------------- helpers ---------------------------------------------------
__device__ __forceinline__ uint32_t smem_u32(const void* p) {
    uint32_t a;
    asm("{ .reg .u64 t; cvta.to.shared.u64 t, %1; cvt.u32.u64 %0, t; }"
        : "=r"(a) : "l"(p));
    return a;
}

static __device__ __forceinline__ uint32_t pack_h2(float a, float b) {
    __half2 t = __floats2half2_rn(a, b);
    return *(uint32_t*)&t;
}

// XOR-swizzled byte offset inside a (rows x 128) fp16 tile (pitch 256B).
__device__ __forceinline__ int swz(int row, int col) {
    return row * 256 + ((((col >> 3) ^ (row & 7)) & 15) << 4) + ((col & 7) << 1);
}

#define LDMX4(r0, r1, r2, r3, addr) \
    asm volatile("ldmatrix.sync.aligned.m8n8.x4.shared.b16 {%0,%1,%2,%3}, [%4];" \
                 : "=r"(r0), "=r"(r1), "=r"(r2), "=r"(r3) : "r"(addr))

#define MMA16816H(c, a, b0, b1) \
    asm volatile( \
        "mma.sync.aligned.m16n8k16.row.col.f32.f16.f16.f32 " \
        "{%0,%1,%2,%3}, {%4,%5,%6,%7}, {%8,%9}, {%0,%1,%2,%3};" \
        : "+f"((c)[0]), "+f"((c)[1]), "+f"((c)[2]), "+f"((c)[3]) \
        : "r"((a)[0]), "r"((a)[1]), "r"((a)[2]), "r"((a)[3]), "r"(b0), "r"(b1))

// SMEM: A fp16 128x128 (32KB) + B fp16 (32KB) = 64KB
#define SM_A 0
#define SM_B 32768
#define SM_TOTAL 65536

// ---------------- x -> fp16 convert (input layer A) --------------------------
__global__ void cvt_x_k(const float* __restrict__ x, __half* __restrict__ xh) {
    int i = blockIdx.x * blockDim.x + threadIdx.x;
    if (i < NN * HH / 4) {
        float4 v = ((const float4*)x)[i];
        uint2 o;
        o.x = pack_h2(v.x, v.y);
        o.y = pack_h2(v.z, v.w);
        ((uint2*)xh)[i] = o;
    }
}

// ---------------- B-tile preparation (once per launch) ----------------------
// Tile t image: Wmma[n][k] = wscale * W[k*H + n] as fp16, swizzled.
// (No identity fold — the GEMM epilogue adds ident*h exactly.)
__global__ __launch_bounds__(256) void prep_b_k(
    const float* __restrict__ W_in, const float* __restrict__ convW,
    const float* __restrict__ W_jk,
    float b0, float b1, float b2, float b3, float b4) {
    int t = blockIdx.x;
    const float* W;
    float wscale;
    if (t == 0) { W = W_in; wscale = 1.f; }
    else if (t <= 5) {
        float blv = (t == 1) ? b0 : (t == 2) ? b1 : (t == 3) ? b2 : (t == 4) ? b3 : b4;
        W = convW + (long)(t - 1) * HH * HH;
        wscale = blv;
    } else { W = W_jk + (long)(t - 6) * HH * HH; wscale = 1.f; }

    int tid = threadIdx.x;
    int n = tid >> 1;
    int kb = (tid & 1) << 6;
    const float* Wb = W + (long)kb * HH + n;
    uint8_t* bp = g_B + (long)t * 32768;
    #pragma unroll
    for (int jj = 0; jj < 8; jj++) {
        int k0 = kb + jj * 8;
        uint4 hv;
        uint32_t* hp = &hv.x;
        #pragma unroll
        for (int q = 0; q < 4; q++) {
            float w0 = wscale * Wb[(long)(jj * 8 + q * 2) * HH];
            float w1 = wscale * Wb[(long)(jj * 8 + q * 2 + 1) * HH];
            hp[q] = pack_h2(w0, w1);
        }
        *(uint4*)(bp + swz(n, k0)) = hv;
    }
}

// ---------------- tensor-core GEMM (fp16 A, fp16 W, 1 term) -----------------
// MODE 0: single chunk +bias.  MODE 1: plain (conv).  MODE 2: 4 chunks +bias.
// IDENT 1: epilogue adds identc * h (read from A smem) -- exact identity term.
// STATS 1: atomicAdd per-column sum/sumsq of final C into g_bnsum/g_bnsq.
// C (fp32) and Ch (fp16) outputs independently nullable.
template <int MODE, int STATS, int IDENT>
__global__ __launch_bounds__(256, 2) void gemm_tc_k(
    const __half* __restrict__ A0, const __half* __restrict__ A1,
    const __half* __restrict__ A2, const __half* __restrict__ A3,
    const float* __restrict__ bias, int tbase, float identc,
    float* __restrict__ C, __half* __restrict__ Ch) {
    extern __shared__ char smem[];
    uint32_t sb = smem_u32(smem);
    const int tid = threadIdx.x;
    const int wid = tid >> 5, lane = tid & 31;
    const int block_row = blockIdx.x * 128;

    const int wm = (wid & 3) * 32;
    const int wn = (wid >> 2) * 64;
    const int lrow = lane & 7, quad = lane >> 3;

    float acc[2][8][4];
    #pragma unroll
    for (int i = 0; i < 2; i++)
        #pragma unroll
        for (int j = 0; j < 8; j++)
            #pragma unroll
            for (int q = 0; q < 4; q++) acc[i][j][q] = 0.f;

    const int NCH = (MODE == 2) ? 4 : 1;
    for (int c = 0; c < NCH; c++) {
        const __half* Ab = (c == 0) ? A0 : (c == 1) ? A1 : (c == 2) ? A2 : A3;
        // ---- A tile fill: straight fp16 copy into swizzled smem ----
        {
            int row = tid >> 1;
            int cb = (tid & 1) << 6;
            int grow = block_row + row;
            const uint4* sp = (const uint4*)(Ab + (long)grow * HH + cb);
            #pragma unroll
            for (int jj = 0; jj < 8; jj++) {
                uint4 u = make_uint4(0u, 0u, 0u, 0u);
                if (grow < NN) u = sp[jj];
                *(uint4*)(smem + SM_A + swz(row, cb + jj * 8)) = u;
            }
        }
        // ---- B tile fill: straight copy of preconverted swizzled image ----
        {
            const uint4* bsrc = (const uint4*)(g_B + (long)(tbase + c) * 32768);
            uint4* bdst = (uint4*)(smem + SM_B);
            #pragma unroll
            for (int s = tid; s < 2048; s += 256) bdst[s] = bsrc[s];
        }
        __syncthreads();

        // ---- compute: single fp16 term ----
        #pragma unroll
        for (int k16 = 0; k16 < 128; k16 += 16) {
            uint32_t a[2][4];
            #pragma unroll
            for (int mt = 0; mt < 2; mt++) {
                int row = wm + mt * 16 + (quad & 1) * 8 + lrow;
                int col = k16 + (quad >> 1) * 8;
                uint32_t addr = sb + SM_A + swz(row, col);
                LDMX4(a[mt][0], a[mt][1], a[mt][2], a[mt][3], addr);
            }
            #pragma unroll
            for (int nb = 0; nb < 4; nb++) {
                int row = wn + nb * 16 + (quad >> 1) * 8 + lrow;
                int col = k16 + (quad & 1) * 8;
                uint32_t addr = sb + SM_B + swz(row, col);
                uint32_t b0, b1, b2, b3;
                LDMX4(b0, b1, b2, b3, addr);
                #pragma unroll
                for (int mt = 0; mt < 2; mt++) {
                    MMA16816H(acc[mt][nb * 2], a[mt], b0, b1);
                    MMA16816H(acc[mt][nb * 2 + 1], a[mt], b2, b3);
                }
            }
        }
        __syncthreads();
    }

    // ---- epilogue: exact identity term from A smem (conv layers) ----
    if (IDENT) {
        #pragma unroll
        for (int mt = 0; mt < 2; mt++) {
            int row0 = wm + mt * 16 + (lane >> 2);   // tile-local rows
            int row1 = row0 + 8;
            #pragma unroll
            for (int nt = 0; nt < 8; nt++) {
                int cb = wn + nt * 8 + (lane & 3) * 2;
                __half2 h0 = *(__half2*)(smem + SM_A + swz(row0, cb));
                __half2 h1 = *(__half2*)(smem + SM_A + swz(row1, cb));
                float2 f0 = __half22float2(h0);
                float2 f1 = __half22float2(h1);
                acc[mt][nt][0] += identc * f0.x;
                acc[mt][nt][1] += identc * f0.y;
                acc[mt][nt][2] += identc * f1.x;
                acc[mt][nt][3] += identc * f1.y;
            }
        }
    }

    // ---- epilogue: store fp32 and/or fp16 ----
    #pragma unroll
    for (int mt = 0; mt < 2; mt++) {
        int r0 = block_row + wm + mt * 16 + (lane >> 2);
        int r1 = r0 + 8;
        #pragma unroll
        for (int nt = 0; nt < 8; nt++) {
            int cb = wn + nt * 8 + (lane & 3) * 2;
            float2 p0, p1;
            p0.x = acc[mt][nt][0]; p0.y = acc[mt][nt][1];
            p1.x = acc[mt][nt][2]; p1.y = acc[mt][nt][3];
            if (MODE != 1) {
                float bx = bias[cb], by = bias[cb + 1];
                p0.x += bx; p0.y += by;
                p1.x += bx; p1.y += by;
            }
            if (r0 < NN) {
                if (C)  *(float2*)(C + (long)r0 * HH + cb) = p0;
                if (Ch) *(uint32_t*)(Ch + (long)r0 * HH + cb) = pack_h2(p0.x, p0.y);
            }
            if (r1 < NN) {
                if (C)  *(float2*)(C + (long)r1 * HH + cb) = p1;
                if (Ch) *(uint32_t*)(Ch + (long)r1 * HH + cb) = pack_h2(p1.x, p1.y);
            }
        }
    }
    // ---- epilogue: fused BN statistics (after ident; padded rows = 0) ----
    if (STATS) {
        #pragma unroll
        for (int nt = 0; nt < 8; nt++) {
            #pragma unroll
            for (int p = 0; p < 2; p++) {
                float a00 = acc[0][nt][p],     a01 = acc[0][nt][2 + p];
                float a10 = acc[1][nt][p],     a11 = acc[1][nt][2 + p];
                float s = (a00 + a01) + (a10 + a11);
                float q = a00 * a00 + a01 * a01 + a10 * a10 + a11 * a11;
                #pragma unroll
                for (int m = 4; m < 32; m <<= 1) {
                    s += __shfl_xor_sync(0xFFFFFFFFu, s, m);
                    q += __shfl_xor_sync(0xFFFFFFFFu, q, m);
                }
                if (lane < 4) {
                    int cb = wn + nt * 8 + lane * 2 + p;
                    atomicAdd(&g_bnsum[cb], s);
                    atomicAdd(&g_bnsq[cb], q);
                }
            }
        }
    }
}

// ---------------- edge-list helpers ----------------------------------------
__device__ __forceinline__ int edge_at(const void* buf, int e) {
    if (g_is64) return (int)((const long long*)buf)[e];
    return ((const int*)buf)[e];
}

__global__ void detect64_k(const void* srcbuf) {
    const unsigned int* p = (const unsigned int*)srcbuf;
    int any = 0;
    for (int i = 1; i < 512; i += 2) any |= (p[i] != 0u);
    g_is64 = any ? 0 : 1;
}

__global__ void zero_csr_k() {
    int i = blockIdx.x * blockDim.x + threadIdx.x;
    if (i < NN) { g_deg[i] = 0; g_cursor[i] = 0; }
}

__global__ void hist_k(const void* dstbuf) {
    for (int e = blockIdx.x * blockDim.x + threadIdx.x; e < EE;
         e += gridDim.x * blockDim.x) {
        atomicAdd(&g_deg[edge_at(dstbuf, e)], 1);
    }
}

__global__ void scanA_k() {
    __shared__ int wt[32];
    int tid = threadIdx.x, lane = tid & 31, wid = tid >> 5;
    int i = blockIdx.x * 1024 + tid;
    int v = (i < NN) ? g_deg[i] : 0;
    int x = v;
    #pragma unroll
    for (int d = 1; d < 32; d <<= 1) {
        int y = __shfl_up_sync(0xFFFFFFFFu, x, d);
        if (lane >= d) x += y;
    }
    if (lane == 31) wt[wid] = x;
    __syncthreads();
    if (wid == 0) {
        int t = wt[lane];
        int tx = t;
        #pragma unroll
        for (int d = 1; d < 32; d <<= 1) {
            int y = __shfl_up_sync(0xFFFFFFFFu, tx, d);
            if (lane >= d) tx += y;
        }
        wt[lane] = tx - t;
    }
    __syncthreads();
    int incl = x + wt[wid];
    if (i < NN) g_rowptr[i] = incl - v;
    if (tid == 1023) g_part[blockIdx.x] = incl;
}

__global__ void scanB_k(int nblk) {
    int s = 0;
    for (int b = 0; b < nblk; b++) { g_partoff[b] = s; s += g_part[b]; }
    g_rowptr[NN] = s;
}

__global__ void scanC_k() {
    int i = blockIdx.x * 1024 + threadIdx.x;
    if (i < NN) g_rowptr[i] += g_partoff[blockIdx.x];
}

__global__ void fill_k(const void* srcbuf, const void* dstbuf) {
    for (int e = blockIdx.x * blockDim.x + threadIdx.x; e < EE;
         e += gridDim.x * blockDim.x) {
        int d = edge_at(dstbuf, e);
        int s = edge_at(srcbuf, e);
        int pos = atomicAdd(&g_cursor[d], 1);
        g_col[g_rowptr[d] + pos] = s;
    }
}

// ------ gather: h = 0.9 * sum_src f(zh[src]) + 0.1 * x0h   (all fp16 I/O) ---
// BNMODE 0: f = identity.  BNMODE 1: f(v) = relu(v * s[c] + t[c]).
template <int BNMODE>
__global__ void gather_k(const __half* __restrict__ zh,
                         const __half* __restrict__ x0h,
                         __half* __restrict__ h) {
    int gw = (blockIdx.x * blockDim.x + threadIdx.x) >> 5;
    if (gw >= NN) return;
    int lane = threadIdx.x & 31;
    float4 s4, t4;
    if (BNMODE) {
        s4 = *(const float4*)(g_bns + lane * 4);
        t4 = *(const float4*)(g_bnt + lane * 4);
    }
    int beg = g_rowptr[gw], end = g_rowptr[gw + 1];
    float4 acc = make_float4(0.f, 0.f, 0.f, 0.f);
    int e = beg;
    #define LD4H(v, p, s) do { \
        uint2 _u = ((const uint2*)((p) + (long)(s) * HH))[lane]; \
        float2 _f01 = __half22float2(*(__half2*)&_u.x); \
        float2 _f23 = __half22float2(*(__half2*)&_u.y); \
        (v).x = _f01.x; (v).y = _f01.y; (v).z = _f23.x; (v).w = _f23.y; } while (0)
    #define XF(v) do { if (BNMODE) { \
        (v).x = fmaxf(fmaf((v).x, s4.x, t4.x), 0.f); \
        (v).y = fmaxf(fmaf((v).y, s4.y, t4.y), 0.f); \
        (v).z = fmaxf(fmaf((v).z, s4.z, t4.z), 0.f); \
        (v).w = fmaxf(fmaf((v).w, s4.w, t4.w), 0.f); } } while (0)
    for (; e + 3 < end; e += 4) {
        int s0 = g_col[e], s1 = g_col[e + 1], s2 = g_col[e + 2], s3 = g_col[e + 3];
        float4 v0, v1, v2, v3;
        LD4H(v0, zh, s0); LD4H(v1, zh, s1); LD4H(v2, zh, s2); LD4H(v3, zh, s3);
        XF(v0); XF(v1); XF(v2); XF(v3);
        acc.x += (v0.x + v1.x) + (v2.x + v3.x);
        acc.y += (v0.y + v1.y) + (v2.y + v3.y);
        acc.z += (v0.z + v1.z) + (v2.z + v3.z);
        acc.w += (v0.w + v1.w) + (v2.w + v3.w);
    }
    for (; e < end; ++e) {
        int s = g_col[e];
        float4 v;
        LD4H(v, zh, s);
        XF(v);
        acc.x += v.x; acc.y += v.y; acc.z += v.z; acc.w += v.w;
    }
    float4 xv;
    LD4H(xv, x0h, gw);
    #undef XF
    #undef LD4H
    const float A1 = 0.9f, A0 = 0.1f;
    float ox = A1 * acc.x + A0 * xv.x;
    float oy = A1 * acc.y + A0 * xv.y;
    float oz = A1 * acc.z + A0 * xv.z;
    float ow = A1 * acc.w + A0 * xv.w;
    uint2 o;
    o.x = pack_h2(ox, oy);
    o.y = pack_h2(oz, ow);
    ((uint2*)(h + (long)gw * HH))[lane] = o;
}

// ---------------- BatchNorm zero + finalize ---------------------------------
__global__ void zero_bn_k() {
    int c = threadIdx.x;
    g_bnsum[c] = 0.f;
    g_bnsq[c] = 0.f;
}

__global__ void finalize_bn_k(const float* __restrict__ gamma,
                              const float* __restrict__ beta) {
    int c = threadIdx.x;
    float invN = 1.0f / (float)NN;
    float m = g_bnsum[c] * invN;
    float var = g_bnsq[c] * invN - m * m;
    float s = rsqrtf(var + 1e-5f) * gamma[c];
    g_bns[c] = s;
    g_bnt[c] = beta[c] - m * s;
}

// ---------------- host orchestration ----------------------------------------
extern "C" void kernel_launch(void* const* d_in, const int* in_sizes, int n_in,
                              void* d_out, int out_size) {
    const float* x     = (const float*)d_in[0];
    const float* W_in  = (const float*)d_in[1];
    const float* b_in  = (const float*)d_in[2];
    const float* convW = (const float*)d_in[3];
    const float* gma   = (const float*)d_in[4];
    const float* bta   = (const float*)d_in[5];
    const float* W_jk  = (const float*)d_in[6];
    const float* b_jk  = (const float*)d_in[7];
    const void*  src   = d_in[8];
    const void*  dst   = d_in[9];
    float* out = (float*)d_out;

    void *ph, *pzh;
    cudaGetSymbolAddress(&ph, g_h);
    cudaGetSymbolAddress(&pzh, g_zh);
    __half* h   = (__half*)ph;
    __half* zh0 = (__half*)pzh;                 // input-layer out (residual)
    __half* zh1 = zh0 + (long)NN * HH;          // conv0 out
    __half* zh2 = zh1 + (long)NN * HH;          // conv1 out
    __half* zh3 = zh2 + (long)NN * HH;          // conv2 out
    __half* zh4 = zh3 + (long)NN * HH;          // conv3 out
    __half* zh5 = zh4 + (long)NN * HH;          // JK out

    float bl[LL];
    for (int i = 0; i < LL; i++) bl[i] = (float)log(0.5 / (double)(i + 1) + 1.0);

    cudaFuncSetAttribute(gemm_tc_k<0, 0, 0>, cudaFuncAttributeMaxDynamicSharedMemorySize, SM_TOTAL);
    cudaFuncSetAttribute(gemm_tc_k<1, 0, 1>, cudaFuncAttributeMaxDynamicSharedMemorySize, SM_TOTAL);
    cudaFuncSetAttribute(gemm_tc_k<1, 1, 1>, cudaFuncAttributeMaxDynamicSharedMemorySize, SM_TOTAL);
    cudaFuncSetAttribute(gemm_tc_k<2, 0, 0>, cudaFuncAttributeMaxDynamicSharedMemorySize, SM_TOTAL);

    const int GEMM_BLOCKS = (NN + 127) / 128;            // 782
    const int GATHER_BLOCKS = (NN * 32 + 255) / 256;
    const int SCAN_BLOCKS = (NN + 1023) / 1024;          // 98

    // ---- forked side stream: CSR build concurrent with prep + input GEMM ----
    cudaStream_t s2;
    cudaStreamCreateWithFlags(&s2, cudaStreamNonBlocking);
    cudaEvent_t evFork, evJoin;
    cudaEventCreateWithFlags(&evFork, cudaEventDisableTiming);
    cudaEventCreateWithFlags(&evJoin, cudaEventDisableTiming);

    cudaEventRecord(evFork, 0);
    cudaStreamWaitEvent(s2, evFork, 0);

    zero_csr_k<<<(NN + 255) / 256, 256, 0, s2>>>();
    detect64_k<<<1, 1, 0, s2>>>(src);
    hist_k<<<1024, 256, 0, s2>>>(dst);
    scanA_k<<<SCAN_BLOCKS, 1024, 0, s2>>>();
    scanB_k<<<1, 1, 0, s2>>>(SCAN_BLOCKS);
    scanC_k<<<SCAN_BLOCKS, 1024, 0, s2>>>();
    fill_k<<<1024, 256, 0, s2>>>(src, dst);
    cudaEventRecord(evJoin, s2);

    // main stream: convert x -> fp16 (g_h scratch), B prep, input GEMM
    cvt_x_k<<<(NN * HH / 4 + 255) / 256, 256>>>(x, h);
    prep_b_k<<<10, 256>>>(W_in, convW, W_jk, bl[0], bl[1], bl[2], bl[3], bl[4]);
    gemm_tc_k<0, 0, 0><<<GEMM_BLOCKS, 256, SM_TOTAL>>>(h, 0, 0, 0, b_in, 0, 0.f,
                                                       0, zh0);

    cudaStreamWaitEvent(0, evJoin, 0);

    const __half* gin[LL]  = {zh0, zh1, zh2, zh3, zh5};  // gather sources
    __half* chout[LL]      = {zh1, zh2, zh3, zh4, 0};    // conv fp16 outputs
    for (int i = 0; i < LL; i++) {
        if (i >= 1 && i <= 3)
            gather_k<1><<<GATHER_BLOCKS, 256>>>(gin[i], zh0, h);
        else
            gather_k<0><<<GATHER_BLOCKS, 256>>>(gin[i], zh0, h);
        float* Cout = (i == 4) ? out : 0;
        float identc = 1.0f - bl[i];
        if (i < 3) {
            zero_bn_k<<<1, HH>>>();
            gemm_tc_k<1, 1, 1><<<GEMM_BLOCKS, 256, SM_TOTAL>>>(h, 0, 0, 0, 0, 1 + i,
                                                               identc, Cout, chout[i]);
            finalize_bn_k<<<1, HH>>>(gma + i * HH, bta + i * HH);
        } else {
            gemm_tc_k<1, 0, 1><<<GEMM_BLOCKS, 256, SM_TOTAL>>>(h, 0, 0, 0, 0, 1 + i,
                                                               identc, Cout, chout[i]);
        }
        if (i == 3) {
            // JK: A = conv0..3 fp16 outputs, writes fp16 only (feeds gather 4)
            gemm_tc_k<2, 0, 0><<<GEMM_BLOCKS, 256, SM_TOTAL>>>(zh1, zh2, zh3, zh4,
                                                               b_jk, 6, 0.f, 0, zh5);
        }
    }

    cudaEventDestroy(evFork);
    cudaEventDestroy(evJoin);
    cudaStreamDestroy(s2);
    (void)in_sizes; (void)n_in; (void)out_size;
}